// round 8
// baseline (speedup 1.0000x reference)
#include <cuda_runtime.h>
#include <cuda_bf16.h>
#include <stdint.h>
#include <math.h>

// ---------------- model dims ----------------
#define B_ 4
#define L_ 1024
#define D_IN 128
#define D_MODEL 512
#define N_LAYERS 2
#define N_CLASSES 3
#define D_INNER 1024
#define D_STATE 64
#define D_CONV 2
#define DT_RANK 32
#define ML (B_ * L_)

// ---------------- scratch (device globals; no allocation) ----------------
__device__ float g_h[ML * D_MODEL];
__device__ float g_xz[ML * 2 * D_INNER];
__device__ float g_xc[ML * D_INNER];
__device__ float g_dbc[ML * 160];
__device__ float g_dt[ML * D_INNER];

// activation planes
__device__ __nv_bfloat16 g_hh[ML * D_MODEL],  g_hl[ML * D_MODEL];
__device__ __nv_bfloat16 g_xch[ML * D_INNER], g_xcl[ML * D_INNER];
__device__ __nv_bfloat16 g_dbch[ML * 160],    g_dbcl[ML * 160];
__device__ __nv_bfloat16 g_yh[ML * D_INNER],  g_yl[ML * D_INNER];
__device__ __nv_bfloat16 g_xh[ML * D_IN],     g_xl[ML * D_IN];

// weight planes (split once per launch, up front)
__device__ __nv_bfloat16 g_expwh[D_MODEL * D_IN],            g_expwl[D_MODEL * D_IN];
__device__ __nv_bfloat16 g_inwh[N_LAYERS * 2 * D_INNER * D_MODEL], g_inwl[N_LAYERS * 2 * D_INNER * D_MODEL];
__device__ __nv_bfloat16 g_xpwh[N_LAYERS * 160 * D_INNER],   g_xpwl[N_LAYERS * 160 * D_INNER];
__device__ __nv_bfloat16 g_dtwh[N_LAYERS * D_INNER * DT_RANK], g_dtwl[N_LAYERS * D_INNER * DT_RANK];
__device__ __nv_bfloat16 g_outwh[N_LAYERS * D_MODEL * D_INNER], g_outwl[N_LAYERS * D_MODEL * D_INNER];

__device__ __forceinline__ float softplus_f(float v) {
    return (v > 20.f) ? v : log1pf(__expf(v));
}
__device__ __forceinline__ void split2(float e0, float e1, unsigned int& hi, unsigned int& lo) {
    __nv_bfloat162 h = __floats2bfloat162_rn(e0, e1);
    float r0 = e0 - __bfloat162float(h.x);
    float r1 = e1 - __bfloat162float(h.y);
    __nv_bfloat162 l = __floats2bfloat162_rn(r0, r1);
    hi = *reinterpret_cast<unsigned int*>(&h);
    lo = *reinterpret_cast<unsigned int*>(&l);
}
__device__ __forceinline__ void mma_bf16(float* c, const unsigned int* a, const unsigned int* b) {
    asm volatile(
        "mma.sync.aligned.m16n8k16.row.col.f32.bf16.bf16.f32 "
        "{%0,%1,%2,%3}, {%4,%5,%6,%7}, {%8,%9}, {%0,%1,%2,%3};\n"
        : "+f"(c[0]), "+f"(c[1]), "+f"(c[2]), "+f"(c[3])
        : "r"(a[0]), "r"(a[1]), "r"(a[2]), "r"(a[3]),
          "r"(b[0]), "r"(b[1]));
}
__device__ __forceinline__ void cp16(unsigned int smem, const void* gmem, int srcbytes) {
    asm volatile("cp.async.cg.shared.global [%0], [%1], 16, %2;\n"
                 :: "r"(smem), "l"(gmem), "r"(srcbytes));
}
__device__ __forceinline__ void ldsm4(unsigned int& r0, unsigned int& r1,
                                      unsigned int& r2, unsigned int& r3, unsigned int addr) {
    asm volatile("ldmatrix.sync.aligned.m8n8.x4.shared.b16 {%0,%1,%2,%3}, [%4];"
                 : "=r"(r0), "=r"(r1), "=r"(r2), "=r"(r3) : "r"(addr));
}

// ---------------- splitter ----------------
__global__ void splitf(const float* __restrict__ src,
                       __nv_bfloat16* __restrict__ hi,
                       __nv_bfloat16* __restrict__ lo, int n)
{
    int i = (blockIdx.x * blockDim.x + threadIdx.x) * 4;
    if (i >= n) return;
    float4 v = *(const float4*)(src + i);
    unsigned int h0, l0, h1, l1;
    split2(v.x, v.y, h0, l0);
    split2(v.z, v.w, h1, l1);
    *(uint2*)(hi + i) = make_uint2(h0, h1);
    *(uint2*)(lo + i) = make_uint2(l0, l1);
}

// ================ ldmatrix split-bf16 GEMM ================
// C(M,N) = A(M,K planes; alda) @ W(N,K planes)^T, 3-term bf16 split, fp32 acc.
// CTA 128x128, BK=64, 256 threads = 8 warps (2m x 4n of 64x32).
// SMEM: per plane 128 rows x 128B, SW128 swizzle; 4 planes/stage, 2 stages.
#define PLANE_B 16384u
#define STAGE_B (4u * PLANE_B)
#define DYN_B   (2u * STAGE_B)

__global__ void __launch_bounds__(256, 1)
gemm_lm(const __nv_bfloat16* __restrict__ Ah, const __nv_bfloat16* __restrict__ Al, int alda,
        const __nv_bfloat16* __restrict__ Wh, const __nv_bfloat16* __restrict__ Wl,
        const float* __restrict__ bias, float* __restrict__ C,
        __nv_bfloat16* __restrict__ Ch, __nv_bfloat16* __restrict__ Cl,
        int M, int N, int K, int act)
{
    extern __shared__ unsigned char dynraw[];
    const int tid = threadIdx.x;
    const int lane = tid & 31, w = tid >> 5;
    const int g = lane >> 2, l4 = lane & 3;
    const int wm = (w >> 2) * 64, wn = (w & 3) * 32;
    const int m0 = blockIdx.y * 128, n0 = blockIdx.x * 128;

    const unsigned int dynbase = (unsigned int)__cvta_generic_to_shared(dynraw);

    // ---- loader geometry: row = tid/2, 4 x 16B chunks at (tid%2)*64B ----
    const int lrow = tid >> 1;
    const int c0 = (tid & 1) * 4;
    const __nv_bfloat16* Ahr = Ah + (long)(m0 + lrow) * alda;
    const __nv_bfloat16* Alr = Al + (long)(m0 + lrow) * alda;
    const int wrow = n0 + lrow;
    const bool wv = wrow < N;
    const __nv_bfloat16* Whr = Wh + (long)(wv ? wrow : 0) * K;
    const __nv_bfloat16* Wlr = Wl + (long)(wv ? wrow : 0) * K;
    unsigned int swo[4];
#pragma unroll
    for (int c = 0; c < 4; c++) {
        unsigned int off = (unsigned int)(lrow * 128 + (c0 + c) * 16);
        swo[c] = off ^ ((off >> 3) & 0x70);
    }

    // ---- ldmatrix lane geometry ----
    const int lrowa = lane & 15;
    const unsigned int kbhi = (unsigned int)((lane >> 4) * 16);
    const unsigned int msk = (unsigned int)((lane & 7) * 16);
    unsigned int aoff[4], boff[2];
#pragma unroll
    for (int i = 0; i < 4; i++) aoff[i] = (unsigned int)((wm + 16 * i + lrowa) * 128);
#pragma unroll
    for (int jp = 0; jp < 2; jp++) boff[jp] = (unsigned int)((wn + 16 * jp + lrowa) * 128);

    float acc[4][4][4];
#pragma unroll
    for (int i = 0; i < 4; i++)
#pragma unroll
        for (int j = 0; j < 4; j++)
#pragma unroll
            for (int e = 0; e < 4; e++) acc[i][j][e] = 0.f;

    const int nch = (K + 63) / 64;

    auto load_chunk = [&](int kc, int s) {
        const unsigned int base = dynbase + (unsigned int)s * STAGE_B;
#pragma unroll
        for (int c = 0; c < 4; c++) {
            int ke = kc * 64 + (c0 + c) * 8;
            int vb = (K - ke) * 2;
            vb = vb < 0 ? 0 : (vb > 16 ? 16 : vb);
            const int kes = vb ? ke : 0;
            const int vbw = wv ? vb : 0;
            cp16(base + swo[c],               Ahr + kes, vb);
            cp16(base + PLANE_B + swo[c],     Alr + kes, vb);
            cp16(base + 2 * PLANE_B + swo[c], Whr + kes, vbw);
            cp16(base + 3 * PLANE_B + swo[c], Wlr + kes, vbw);
        }
        asm volatile("cp.async.commit_group;\n");
    };

    load_chunk(0, 0);
    if (nch > 1) load_chunk(1, 1);

    for (int it = 0; it < nch; it++) {
        const int s = it & 1;
        if (it + 1 < nch) asm volatile("cp.async.wait_group 1;\n");
        else              asm volatile("cp.async.wait_group 0;\n");
        __syncthreads();

        const unsigned int base = dynbase + (unsigned int)s * STAGE_B;
#pragma unroll
        for (int ks = 0; ks < 4; ks++) {
            const unsigned int kt = ((unsigned int)(ks * 32) | kbhi) ^ msk;
            unsigned int bh[2][4], bl[2][4];
#pragma unroll
            for (int jp = 0; jp < 2; jp++) {
                ldsm4(bh[jp][0], bh[jp][1], bh[jp][2], bh[jp][3],
                      base + 2 * PLANE_B + boff[jp] + kt);
                ldsm4(bl[jp][0], bl[jp][1], bl[jp][2], bl[jp][3],
                      base + 3 * PLANE_B + boff[jp] + kt);
            }
#pragma unroll
            for (int i = 0; i < 4; i++) {
                unsigned int ah[4], al[4];
                ldsm4(ah[0], ah[1], ah[2], ah[3], base + aoff[i] + kt);
                ldsm4(al[0], al[1], al[2], al[3], base + PLANE_B + aoff[i] + kt);
#pragma unroll
                for (int jp = 0; jp < 2; jp++) {
                    unsigned int b0h[2] = { bh[jp][0], bh[jp][2] };
                    unsigned int b1h[2] = { bh[jp][1], bh[jp][3] };
                    unsigned int b0l[2] = { bl[jp][0], bl[jp][2] };
                    unsigned int b1l[2] = { bl[jp][1], bl[jp][3] };
                    mma_bf16(acc[i][2 * jp],     ah, b0h);
                    mma_bf16(acc[i][2 * jp + 1], ah, b1h);
                    mma_bf16(acc[i][2 * jp],     ah, b0l);
                    mma_bf16(acc[i][2 * jp + 1], ah, b1l);
                    mma_bf16(acc[i][2 * jp],     al, b0h);
                    mma_bf16(acc[i][2 * jp + 1], al, b1h);
                }
            }
        }
        __syncthreads();
        if (it + 2 < nch) load_chunk(it + 2, s);
    }

    // epilogue (c layout: rows g/g+8, cols 2*l4, 2*l4+1)
#pragma unroll
    for (int i = 0; i < 4; i++) {
        const int mr0 = m0 + wm + 16 * i + g;
        const int mr1 = mr0 + 8;
#pragma unroll
        for (int j = 0; j < 4; j++) {
            const int n = n0 + wn + 8 * j + 2 * l4;
            if (n < N) {
                float b0 = 0.f, b1 = 0.f;
                if (bias) { b0 = bias[n]; b1 = bias[n + 1]; }
                float v0 = acc[i][j][0] + b0, v1 = acc[i][j][1] + b1;
                float v2 = acc[i][j][2] + b0, v3 = acc[i][j][3] + b1;
                if (act == 1) {
                    v0 = softplus_f(v0); v1 = softplus_f(v1);
                    v2 = softplus_f(v2); v3 = softplus_f(v3);
                }
                *(float2*)(C + (long)mr0 * N + n) = make_float2(v0, v1);
                *(float2*)(C + (long)mr1 * N + n) = make_float2(v2, v3);
                if (Ch) {
                    unsigned int ph, pl;
                    split2(v0, v1, ph, pl);
                    *(unsigned int*)(Ch + (long)mr0 * N + n) = ph;
                    *(unsigned int*)(Cl + (long)mr0 * N + n) = pl;
                    split2(v2, v3, ph, pl);
                    *(unsigned int*)(Ch + (long)mr1 * N + n) = ph;
                    *(unsigned int*)(Cl + (long)mr1 * N + n) = pl;
                }
            }
        }
    }
}

// ---------------- conv (D_CONV=2) + silu ----------------
__global__ void conv_silu_kernel(const float* __restrict__ xz,
                                 const float* __restrict__ cw,
                                 const float* __restrict__ cb,
                                 float* __restrict__ xc,
                                 __nv_bfloat16* __restrict__ xch,
                                 __nv_bfloat16* __restrict__ xcl)
{
    int idx = blockIdx.x * blockDim.x + threadIdx.x;
    if (idx >= ML * D_INNER) return;
    int d = idx & (D_INNER - 1);
    int row = idx >> 10;
    int tt = row & (L_ - 1);
    float cur = xz[(long)row * (2 * D_INNER) + d];
    float prev = (tt > 0) ? xz[(long)(row - 1) * (2 * D_INNER) + d] : 0.f;
    float v = prev * cw[d * 2 + 0] + cur * cw[d * 2 + 1] + cb[d];
    float sv = v / (1.f + __expf(-v));
    xc[idx] = sv;
    __nv_bfloat16 h = __float2bfloat16_rn(sv);
    xch[idx] = h;
    xcl[idx] = __float2bfloat16_rn(sv - __bfloat162float(h));
}

// ---------------- selective scan ----------------
__global__ __launch_bounds__(128)
void scan_kernel(const float* __restrict__ dt, const float* __restrict__ xc,
                 const float* __restrict__ dbc, const float* __restrict__ xz,
                 const float* __restrict__ A_log, const float* __restrict__ Dp,
                 __nv_bfloat16* __restrict__ yh, __nv_bfloat16* __restrict__ yl)
{
    const int gw = (blockIdx.x * blockDim.x + threadIdx.x) >> 5;
    const int lane = threadIdx.x & 31;
    const int b = gw >> 10;
    const int d = gw & (D_INNER - 1);

    const float A0 = -__expf(A_log[d * D_STATE + 2 * lane]);
    const float A1 = -__expf(A_log[d * D_STATE + 2 * lane + 1]);
    const float Dd = Dp[d];

    const float* dtp = dt + (long)b * L_ * D_INNER + d;
    const float* xp  = xc + (long)b * L_ * D_INNER + d;
    const float* bcp = dbc + (long)b * L_ * 160 + DT_RANK + 2 * lane;
    const float* zp  = xz + (long)b * L_ * (2 * D_INNER) + D_INNER + d;
    __nv_bfloat16* yph = yh + (long)b * L_ * D_INNER + d;
    __nv_bfloat16* ypl = yl + (long)b * L_ * D_INNER + d;

    float h0 = 0.f, h1 = 0.f;
    for (int t = 0; t < L_; t++) {
        const float dtv = dtp[t * D_INNER];
        const float xv  = xp[t * D_INNER];
        const float2 Bv = *(const float2*)(bcp + t * 160);
        const float2 Cv = *(const float2*)(bcp + t * 160 + D_STATE);
        const float u = dtv * xv;
        h0 = h0 * __expf(dtv * A0) + u * Bv.x;
        h1 = h1 * __expf(dtv * A1) + u * Bv.y;
        float p = h0 * Cv.x + h1 * Cv.y;
#pragma unroll
        for (int o = 16; o; o >>= 1) p += __shfl_xor_sync(0xffffffffu, p, o);
        if (lane == 0) {
            const float zv = zp[t * (2 * D_INNER)];
            const float yv = (p + xv * Dd) * (zv / (1.f + __expf(-zv)));
            __nv_bfloat16 hh = __float2bfloat16_rn(yv);
            yph[t * D_INNER] = hh;
            ypl[t * D_INNER] = __float2bfloat16_rn(yv - __bfloat162float(hh));
        }
    }
}

// ---------------- final FC ----------------
__global__ void fc_kernel(const float* __restrict__ h, const float* __restrict__ fc_w,
                          const float* __restrict__ fc_b, float* __restrict__ out)
{
    const int w = threadIdx.x >> 5;
    const int lane = threadIdx.x & 31;
    if (w >= B_ * N_CLASSES) return;
    const int b = w / N_CLASSES, c = w % N_CLASSES;
    const float* hp = h + (long)(b * L_ + (L_ - 1)) * D_MODEL;
    float s = 0.f;
    for (int k = lane; k < D_MODEL; k += 32) s += hp[k] * fc_w[c * D_MODEL + k];
#pragma unroll
    for (int o = 16; o; o >>= 1) s += __shfl_xor_sync(0xffffffffu, s, o);
    if (lane == 0) out[b * N_CLASSES + c] = s + fc_b[c];
}

// ---------------- launch ----------------
extern "C" void kernel_launch(void* const* d_in, const int* in_sizes, int n_in,
                              void* d_out, int out_size)
{
    const float* x        = (const float*)d_in[0];
    const float* exp_w    = (const float*)d_in[1];
    const float* exp_b    = (const float*)d_in[2];
    const float* in_w     = (const float*)d_in[3];
    const float* conv_w   = (const float*)d_in[4];
    const float* conv_b   = (const float*)d_in[5];
    const float* xproj_w  = (const float*)d_in[6];
    const float* dtproj_w = (const float*)d_in[7];
    const float* dtproj_b = (const float*)d_in[8];
    const float* A_log    = (const float*)d_in[9];
    const float* Dp       = (const float*)d_in[10];
    const float* out_w    = (const float*)d_in[11];
    const float* fc_w     = (const float*)d_in[12];
    const float* fc_b     = (const float*)d_in[13];
    float* out = (float*)d_out;

    float *ph, *pxz, *pxc, *pdbc, *pdt;
    __nv_bfloat16 *phh, *phl, *pxch, *pxcl, *pdbch, *pdbcl, *pyh, *pyl, *pxh, *pxl;
    __nv_bfloat16 *pexpwh, *pexpwl, *pinwh, *pinwl, *pxpwh, *pxpwl, *pdtwh, *pdtwl, *poutwh, *poutwl;
    cudaGetSymbolAddress((void**)&ph,     g_h);
    cudaGetSymbolAddress((void**)&pxz,    g_xz);
    cudaGetSymbolAddress((void**)&pxc,    g_xc);
    cudaGetSymbolAddress((void**)&pdbc,   g_dbc);
    cudaGetSymbolAddress((void**)&pdt,    g_dt);
    cudaGetSymbolAddress((void**)&phh,    g_hh);
    cudaGetSymbolAddress((void**)&phl,    g_hl);
    cudaGetSymbolAddress((void**)&pxch,   g_xch);
    cudaGetSymbolAddress((void**)&pxcl,   g_xcl);
    cudaGetSymbolAddress((void**)&pdbch,  g_dbch);
    cudaGetSymbolAddress((void**)&pdbcl,  g_dbcl);
    cudaGetSymbolAddress((void**)&pyh,    g_yh);
    cudaGetSymbolAddress((void**)&pyl,    g_yl);
    cudaGetSymbolAddress((void**)&pxh,    g_xh);
    cudaGetSymbolAddress((void**)&pxl,    g_xl);
    cudaGetSymbolAddress((void**)&pexpwh, g_expwh);
    cudaGetSymbolAddress((void**)&pexpwl, g_expwl);
    cudaGetSymbolAddress((void**)&pinwh,  g_inwh);
    cudaGetSymbolAddress((void**)&pinwl,  g_inwl);
    cudaGetSymbolAddress((void**)&pxpwh,  g_xpwh);
    cudaGetSymbolAddress((void**)&pxpwl,  g_xpwl);
    cudaGetSymbolAddress((void**)&pdtwh,  g_dtwh);
    cudaGetSymbolAddress((void**)&pdtwl,  g_dtwl);
    cudaGetSymbolAddress((void**)&poutwh, g_outwh);
    cudaGetSymbolAddress((void**)&poutwl, g_outwl);

    cudaFuncSetAttribute(gemm_lm, cudaFuncAttributeMaxDynamicSharedMemorySize, DYN_B);

    // --- one-time splits (weights + input), all independent ---
    splitf<<<(ML * D_IN / 4 + 255) / 256, 256>>>(x, pxh, pxl, ML * D_IN);
    splitf<<<(D_MODEL * D_IN / 4 + 255) / 256, 256>>>(exp_w, pexpwh, pexpwl, D_MODEL * D_IN);
    splitf<<<(N_LAYERS * 2 * D_INNER * D_MODEL / 4 + 255) / 256, 256>>>(
        in_w, pinwh, pinwl, N_LAYERS * 2 * D_INNER * D_MODEL);
    splitf<<<(N_LAYERS * 160 * D_INNER / 4 + 255) / 256, 256>>>(
        xproj_w, pxpwh, pxpwl, N_LAYERS * 160 * D_INNER);
    splitf<<<(N_LAYERS * D_INNER * DT_RANK / 4 + 255) / 256, 256>>>(
        dtproj_w, pdtwh, pdtwl, N_LAYERS * D_INNER * DT_RANK);
    splitf<<<(N_LAYERS * D_MODEL * D_INNER / 4 + 255) / 256, 256>>>(
        out_w, poutwh, poutwl, N_LAYERS * D_MODEL * D_INNER);

    // embed: h = x @ exp_w^T + exp_b   (4096 x 512, K=128)
    gemm_lm<<<dim3(D_MODEL / 128, ML / 128), 256, DYN_B>>>(pxh, pxl, D_IN, pexpwh, pexpwl,
                                                           exp_b, ph, phh, phl,
                                                           ML, D_MODEL, D_IN, 0);

    for (int l = 0; l < N_LAYERS; l++) {
        const float* conv_w_l = conv_w   + (long)l * D_INNER * D_CONV;
        const float* conv_b_l = conv_b   + (long)l * D_INNER;
        const float* dtb_l    = dtproj_b + (long)l * D_INNER;
        const float* Alog_l   = A_log    + (long)l * D_INNER * D_STATE;
        const float* Dp_l     = Dp       + (long)l * D_INNER;

        const __nv_bfloat16* inwh_l  = pinwh  + (long)l * 2 * D_INNER * D_MODEL;
        const __nv_bfloat16* inwl_l  = pinwl  + (long)l * 2 * D_INNER * D_MODEL;
        const __nv_bfloat16* xpwh_l  = pxpwh  + (long)l * 160 * D_INNER;
        const __nv_bfloat16* xpwl_l  = pxpwl  + (long)l * 160 * D_INNER;
        const __nv_bfloat16* dtwh_l  = pdtwh  + (long)l * D_INNER * DT_RANK;
        const __nv_bfloat16* dtwl_l  = pdtwl  + (long)l * D_INNER * DT_RANK;
        const __nv_bfloat16* outwh_l = poutwh + (long)l * D_MODEL * D_INNER;
        const __nv_bfloat16* outwl_l = poutwl + (long)l * D_MODEL * D_INNER;

        // xz = h @ in_w^T   (4096 x 2048, K=512)
        gemm_lm<<<dim3(2 * D_INNER / 128, ML / 128), 256, DYN_B>>>(
            phh, phl, D_MODEL, inwh_l, inwl_l, nullptr, pxz, nullptr, nullptr,
            ML, 2 * D_INNER, D_MODEL, 0);
        // conv + silu
        conv_silu_kernel<<<(ML * D_INNER + 255) / 256, 256>>>(pxz, conv_w_l, conv_b_l,
                                                              pxc, pxch, pxcl);
        // dbc = xc @ xproj^T  (4096 x 160, K=1024)
        gemm_lm<<<dim3(2, ML / 128), 256, DYN_B>>>(
            pxch, pxcl, D_INNER, xpwh_l, xpwl_l, nullptr, pdbc, pdbch, pdbcl,
            ML, 160, D_INNER, 0);
        // dt = softplus(dbc[:, :32] @ dtproj^T + b)  (4096 x 1024, K=32, alda=160)
        gemm_lm<<<dim3(D_INNER / 128, ML / 128), 256, DYN_B>>>(
            pdbch, pdbcl, 160, dtwh_l, dtwl_l, dtb_l, pdt, nullptr, nullptr,
            ML, D_INNER, DT_RANK, 1);
        // selective scan -> y planes
        scan_kernel<<<(B_ * D_INNER) / 4, 128>>>(pdt, pxc, pdbc, pxz, Alog_l, Dp_l, pyh, pyl);
        // h = y @ out_w^T  (4096 x 512, K=1024)
        gemm_lm<<<dim3(D_MODEL / 128, ML / 128), 256, DYN_B>>>(
            pyh, pyl, D_INNER, outwh_l, outwl_l, nullptr, ph, phh, phl,
            ML, D_MODEL, D_INNER, 0);
    }

    fc_kernel<<<1, 384>>>(ph, fc_w, fc_b, out);
}

// round 9
// speedup vs baseline: 1.9220x; 1.9220x over previous
#include <cuda_runtime.h>
#include <cuda_bf16.h>
#include <stdint.h>
#include <math.h>

// ---------------- model dims ----------------
#define B_ 4
#define L_ 1024
#define D_IN 128
#define D_MODEL 512
#define N_LAYERS 2
#define N_CLASSES 3
#define D_INNER 1024
#define D_STATE 64
#define D_CONV 2
#define DT_RANK 32
#define ML (B_ * L_)

// ---------------- scratch (device globals; no allocation) ----------------
__device__ float g_h[ML * D_MODEL];
__device__ float g_xz[ML * 2 * D_INNER];
__device__ float g_xc[ML * D_INNER];
__device__ float g_dbc[ML * 160];
__device__ float g_dt[ML * D_INNER];
__device__ float g_y[ML * D_INNER];
// transposed [b][d][t] views
__device__ float g_dtT[ML * D_INNER];
__device__ float g_xcT[ML * D_INNER];
__device__ float g_zT[ML * D_INNER];
__device__ float g_yT[ML * D_INNER];

__device__ __forceinline__ float softplus_f(float v) {
    return (v > 20.f) ? v : log1pf(__expf(v));
}
__device__ __forceinline__ void split2(float e0, float e1, unsigned int& hi, unsigned int& lo) {
    __nv_bfloat162 h = __floats2bfloat162_rn(e0, e1);
    float r0 = e0 - __bfloat162float(h.x);
    float r1 = e1 - __bfloat162float(h.y);
    __nv_bfloat162 l = __floats2bfloat162_rn(r0, r1);
    hi = *reinterpret_cast<unsigned int*>(&h);
    lo = *reinterpret_cast<unsigned int*>(&l);
}
__device__ __forceinline__ void mma_bf16(float* c, const unsigned int* a, const unsigned int* b) {
    asm volatile(
        "mma.sync.aligned.m16n8k16.row.col.f32.bf16.bf16.f32 "
        "{%0,%1,%2,%3}, {%4,%5,%6,%7}, {%8,%9}, {%0,%1,%2,%3};\n"
        : "+f"(c[0]), "+f"(c[1]), "+f"(c[2]), "+f"(c[3])
        : "r"(a[0]), "r"(a[1]), "r"(a[2]), "r"(a[3]),
          "r"(b[0]), "r"(b[1]));
}

// ---------------- split-bf16 (3-term) GEMM (R5, best measured) ----------------
// CTA 128x128, BK=32, 256 threads = 8 warps of 64x32; staging split in-kernel.
#define SKW 20

__global__ __launch_bounds__(256, 2)
void gemm3b(const float* __restrict__ A, const float* __restrict__ W,
            const float* __restrict__ bias, float* __restrict__ C,
            int M, int N, int K, int lda, int act)
{
    __shared__ unsigned int SH[2][4][128][SKW];

    const int tid = threadIdx.x;
    const int lane = tid & 31, w = tid >> 5;
    const int g = lane >> 2, l4 = lane & 3;
    const int wm = (w >> 2) * 64, wn = (w & 3) * 32;
    const int m0 = blockIdx.y * 128, n0 = blockIdx.x * 128;

    const int lrow = tid >> 1;
    const int lcolf = (tid & 1) * 16;
    const int p0 = lcolf >> 1;
    const float* Ag = A + (long)(m0 + lrow) * lda + lcolf;
    const int wrow = n0 + lrow;
    const float* Wg = W + (long)(wrow < N ? wrow : 0) * K + lcolf;

    float4 ra[4], rw[4];

    float acc[4][4][4];
#pragma unroll
    for (int i = 0; i < 4; i++)
#pragma unroll
        for (int j = 0; j < 4; j++)
#pragma unroll
            for (int e = 0; e < 4; e++) acc[i][j][e] = 0.f;

    const int niter = K / 32;

#pragma unroll
    for (int q = 0; q < 4; q++) {
        ra[q] = *(const float4*)(Ag + q * 4);
        rw[q] = *(const float4*)(Wg + q * 4);
    }
#pragma unroll
    for (int q = 0; q < 4; q++) {
        unsigned int h0, l0, h1, l1;
        split2(ra[q].x, ra[q].y, h0, l0);
        split2(ra[q].z, ra[q].w, h1, l1);
        SH[0][0][lrow][p0 + 2*q]     = h0;
        SH[0][0][lrow][p0 + 2*q + 1] = h1;
        SH[0][1][lrow][p0 + 2*q]     = l0;
        SH[0][1][lrow][p0 + 2*q + 1] = l1;
        split2(rw[q].x, rw[q].y, h0, l0);
        split2(rw[q].z, rw[q].w, h1, l1);
        SH[0][2][lrow][p0 + 2*q]     = h0;
        SH[0][2][lrow][p0 + 2*q + 1] = h1;
        SH[0][3][lrow][p0 + 2*q]     = l0;
        SH[0][3][lrow][p0 + 2*q + 1] = l1;
    }
    __syncthreads();

    for (int it = 0; it < niter; it++) {
        const int s = it & 1;
        if (it + 1 < niter) {
            const int k0 = (it + 1) * 32;
#pragma unroll
            for (int q = 0; q < 4; q++) {
                ra[q] = *(const float4*)(Ag + k0 + q * 4);
                rw[q] = *(const float4*)(Wg + k0 + q * 4);
            }
        }

#pragma unroll
        for (int ks = 0; ks < 2; ks++) {
            const int kb = ks * 8 + l4;
            unsigned int bh[4][2], bl[4][2];
#pragma unroll
            for (int j = 0; j < 4; j++) {
                const int r = wn + 8 * j + g;
                bh[j][0] = SH[s][2][r][kb];
                bh[j][1] = SH[s][2][r][kb + 4];
                bl[j][0] = SH[s][3][r][kb];
                bl[j][1] = SH[s][3][r][kb + 4];
            }
#pragma unroll
            for (int i = 0; i < 4; i++) {
                const int r0 = wm + 16 * i + g, r1 = r0 + 8;
                unsigned int ah[4], al[4];
                ah[0] = SH[s][0][r0][kb];     ah[1] = SH[s][0][r1][kb];
                ah[2] = SH[s][0][r0][kb + 4]; ah[3] = SH[s][0][r1][kb + 4];
                al[0] = SH[s][1][r0][kb];     al[1] = SH[s][1][r1][kb];
                al[2] = SH[s][1][r0][kb + 4]; al[3] = SH[s][1][r1][kb + 4];
#pragma unroll
                for (int j = 0; j < 4; j++) mma_bf16(acc[i][j], ah, bh[j]);
#pragma unroll
                for (int j = 0; j < 4; j++) mma_bf16(acc[i][j], ah, bl[j]);
#pragma unroll
                for (int j = 0; j < 4; j++) mma_bf16(acc[i][j], al, bh[j]);
            }
        }

        if (it + 1 < niter) {
            const int s2 = (it + 1) & 1;
#pragma unroll
            for (int q = 0; q < 4; q++) {
                unsigned int h0, l0, h1, l1;
                split2(ra[q].x, ra[q].y, h0, l0);
                split2(ra[q].z, ra[q].w, h1, l1);
                SH[s2][0][lrow][p0 + 2*q]     = h0;
                SH[s2][0][lrow][p0 + 2*q + 1] = h1;
                SH[s2][1][lrow][p0 + 2*q]     = l0;
                SH[s2][1][lrow][p0 + 2*q + 1] = l1;
                split2(rw[q].x, rw[q].y, h0, l0);
                split2(rw[q].z, rw[q].w, h1, l1);
                SH[s2][2][lrow][p0 + 2*q]     = h0;
                SH[s2][2][lrow][p0 + 2*q + 1] = h1;
                SH[s2][3][lrow][p0 + 2*q]     = l0;
                SH[s2][3][lrow][p0 + 2*q + 1] = l1;
            }
        }
        __syncthreads();
    }

#pragma unroll
    for (int i = 0; i < 4; i++) {
        const int mr0 = m0 + wm + 16 * i + g;
        const int mr1 = mr0 + 8;
#pragma unroll
        for (int j = 0; j < 4; j++) {
            const int n = n0 + wn + 8 * j + 2 * l4;
            if (n < N) {
                float b0 = 0.f, b1 = 0.f;
                if (bias) { b0 = bias[n]; b1 = bias[n + 1]; }
                float v0 = acc[i][j][0] + b0, v1 = acc[i][j][1] + b1;
                float v2 = acc[i][j][2] + b0, v3 = acc[i][j][3] + b1;
                if (act == 1) {
                    v0 = softplus_f(v0); v1 = softplus_f(v1);
                    v2 = softplus_f(v2); v3 = softplus_f(v3);
                }
                *(float2*)(C + (long)mr0 * N + n) = make_float2(v0, v1);
                *(float2*)(C + (long)mr1 * N + n) = make_float2(v2, v3);
            }
        }
    }
}

// ---------------- 32x32 SMEM-tile transpose: dst[c][r] = src[r][c], per-b 1024x1024
__global__ void transpose_k(const float* __restrict__ src, float* __restrict__ dst,
                            int src_stride, int src_off, int dst_stride)
{
    __shared__ float tile[32][33];
    const int b = blockIdx.z;
    const int r0 = blockIdx.y * 32;
    const int c0 = blockIdx.x * 32;
    const float* s = src + (long)b * 1024 * src_stride + src_off;
    float* dd = dst + (long)b * 1024 * dst_stride;
    const int tx = threadIdx.x, ty = threadIdx.y;
#pragma unroll
    for (int r = ty; r < 32; r += 8)
        tile[r][tx] = s[(long)(r0 + r) * src_stride + c0 + tx];
    __syncthreads();
#pragma unroll
    for (int r = ty; r < 32; r += 8)
        dd[(long)(c0 + r) * dst_stride + r0 + tx] = tile[tx][r];
}

// ---------------- conv (D_CONV=2) + silu ----------------
__global__ void conv_silu_kernel(const float* __restrict__ xz,
                                 const float* __restrict__ cw,
                                 const float* __restrict__ cb,
                                 float* __restrict__ xc)
{
    int idx = blockIdx.x * blockDim.x + threadIdx.x;
    if (idx >= ML * D_INNER) return;
    int d = idx & (D_INNER - 1);
    int row = idx >> 10;
    int tt = row & (L_ - 1);
    float cur = xz[(long)row * (2 * D_INNER) + d];
    float prev = (tt > 0) ? xz[(long)(row - 1) * (2 * D_INNER) + d] : 0.f;
    float v = prev * cw[d * 2 + 0] + cur * cw[d * 2 + 1] + cb[d];
    xc[idx] = v / (1.f + __expf(-v));
}

// ---------------- selective scan v2: transposed inputs, prefetched ----------
__global__ __launch_bounds__(128)
void scan2(const float* __restrict__ dtT, const float* __restrict__ xcT,
           const float* __restrict__ zT, const float* __restrict__ dbc,
           const float* __restrict__ A_log, const float* __restrict__ Dp,
           float* __restrict__ yT)
{
    const int gw = (blockIdx.x * blockDim.x + threadIdx.x) >> 5;
    const int lane = threadIdx.x & 31;
    const int b = gw >> 10;
    const int d = gw & (D_INNER - 1);

    const float A0 = -__expf(A_log[d * D_STATE + 2 * lane]);
    const float A1 = -__expf(A_log[d * D_STATE + 2 * lane + 1]);
    const float Dd = Dp[d];

    const long cd = (long)b * D_INNER + d;
    const float* dtp = dtT + cd * L_;
    const float* xp  = xcT + cd * L_;
    const float* zp  = zT  + cd * L_;
    const float* bcp = dbc + (long)b * L_ * 160 + DT_RANK + 2 * lane;
    float* yp = yT + cd * L_;

    float h0 = 0.f, h1 = 0.f;
    float4 d4 = *(const float4*)dtp;
    float4 x4 = *(const float4*)xp;
    float4 z4 = *(const float4*)zp;
    float2 Bv = *(const float2*)bcp;
    float2 Cv = *(const float2*)(bcp + D_STATE);

    for (int t4 = 0; t4 < L_; t4 += 4) {
        const int tn = (t4 + 4 < L_) ? (t4 + 4) : t4;
        float4 d4n = *(const float4*)(dtp + tn);
        float4 x4n = *(const float4*)(xp + tn);
        float4 z4n = *(const float4*)(zp + tn);
        float da[4], xa[4], za[4], ya[4];
        *(float4*)da = d4; *(float4*)xa = x4; *(float4*)za = z4;
#pragma unroll
        for (int s = 0; s < 4; s++) {
            const int t = t4 + s;
            const int tp1 = (t + 1 < L_) ? (t + 1) : t;
            const float2 Bn = *(const float2*)(bcp + tp1 * 160);
            const float2 Cn = *(const float2*)(bcp + tp1 * 160 + D_STATE);
            const float dtv = da[s], xv = xa[s];
            const float u = dtv * xv;
            h0 = fmaf(h0, __expf(dtv * A0), u * Bv.x);
            h1 = fmaf(h1, __expf(dtv * A1), u * Bv.y);
            float p = h0 * Cv.x + h1 * Cv.y;
#pragma unroll
            for (int o = 16; o; o >>= 1) p += __shfl_xor_sync(0xffffffffu, p, o);
            const float zv = za[s];
            ya[s] = (p + xv * Dd) * (zv / (1.f + __expf(-zv)));
            Bv = Bn; Cv = Cn;
        }
        if (lane == 0) *(float4*)(yp + t4) = *(const float4*)ya;
        d4 = d4n; x4 = x4n; z4 = z4n;
    }
}

// ---------------- final FC ----------------
__global__ void fc_kernel(const float* __restrict__ h, const float* __restrict__ fc_w,
                          const float* __restrict__ fc_b, float* __restrict__ out)
{
    const int w = threadIdx.x >> 5;
    const int lane = threadIdx.x & 31;
    if (w >= B_ * N_CLASSES) return;
    const int b = w / N_CLASSES, c = w % N_CLASSES;
    const float* hp = h + (long)(b * L_ + (L_ - 1)) * D_MODEL;
    float s = 0.f;
    for (int k = lane; k < D_MODEL; k += 32) s += hp[k] * fc_w[c * D_MODEL + k];
#pragma unroll
    for (int o = 16; o; o >>= 1) s += __shfl_xor_sync(0xffffffffu, s, o);
    if (lane == 0) out[b * N_CLASSES + c] = s + fc_b[c];
}

// ---------------- launch ----------------
extern "C" void kernel_launch(void* const* d_in, const int* in_sizes, int n_in,
                              void* d_out, int out_size)
{
    const float* x        = (const float*)d_in[0];
    const float* exp_w    = (const float*)d_in[1];
    const float* exp_b    = (const float*)d_in[2];
    const float* in_w     = (const float*)d_in[3];
    const float* conv_w   = (const float*)d_in[4];
    const float* conv_b   = (const float*)d_in[5];
    const float* xproj_w  = (const float*)d_in[6];
    const float* dtproj_w = (const float*)d_in[7];
    const float* dtproj_b = (const float*)d_in[8];
    const float* A_log    = (const float*)d_in[9];
    const float* Dp       = (const float*)d_in[10];
    const float* out_w    = (const float*)d_in[11];
    const float* fc_w     = (const float*)d_in[12];
    const float* fc_b     = (const float*)d_in[13];
    float* out = (float*)d_out;

    float *ph, *pxz, *pxc, *pdbc, *pdt, *py, *pdtT, *pxcT, *pzT, *pyT;
    cudaGetSymbolAddress((void**)&ph,   g_h);
    cudaGetSymbolAddress((void**)&pxz,  g_xz);
    cudaGetSymbolAddress((void**)&pxc,  g_xc);
    cudaGetSymbolAddress((void**)&pdbc, g_dbc);
    cudaGetSymbolAddress((void**)&pdt,  g_dt);
    cudaGetSymbolAddress((void**)&py,   g_y);
    cudaGetSymbolAddress((void**)&pdtT, g_dtT);
    cudaGetSymbolAddress((void**)&pxcT, g_xcT);
    cudaGetSymbolAddress((void**)&pzT,  g_zT);
    cudaGetSymbolAddress((void**)&pyT,  g_yT);

    const dim3 tgrid(32, 32, 4), tblk(32, 8);

    // embed: h = x @ exp_w^T + exp_b   (4096 x 512, K=128)
    gemm3b<<<dim3(D_MODEL / 128, ML / 128), 256>>>(x, exp_w, exp_b, ph,
                                                   ML, D_MODEL, D_IN, D_IN, 0);

    for (int l = 0; l < N_LAYERS; l++) {
        const float* in_w_l   = in_w     + (long)l * 2 * D_INNER * D_MODEL;
        const float* conv_w_l = conv_w   + (long)l * D_INNER * D_CONV;
        const float* conv_b_l = conv_b   + (long)l * D_INNER;
        const float* xproj_l  = xproj_w  + (long)l * 160 * D_INNER;
        const float* dtw_l    = dtproj_w + (long)l * D_INNER * DT_RANK;
        const float* dtb_l    = dtproj_b + (long)l * D_INNER;
        const float* Alog_l   = A_log    + (long)l * D_INNER * D_STATE;
        const float* Dp_l     = Dp       + (long)l * D_INNER;
        const float* out_w_l  = out_w    + (long)l * D_MODEL * D_INNER;

        // xz = h @ in_w^T   (4096 x 2048, K=512)
        gemm3b<<<dim3(2 * D_INNER / 128, ML / 128), 256>>>(ph, in_w_l, nullptr, pxz,
                                                           ML, 2 * D_INNER, D_MODEL, D_MODEL, 0);
        // z transpose from xz (col offset D_INNER, stride 2048)
        transpose_k<<<tgrid, tblk>>>(pxz, pzT, 2 * D_INNER, D_INNER, L_);
        // conv + silu -> xc, then transpose xc
        conv_silu_kernel<<<(ML * D_INNER + 255) / 256, 256>>>(pxz, conv_w_l, conv_b_l, pxc);
        transpose_k<<<tgrid, tblk>>>(pxc, pxcT, D_INNER, 0, L_);
        // dbc = xc @ xproj^T  (4096 x 160, K=1024)
        gemm3b<<<dim3(2, ML / 128), 256>>>(pxc, xproj_l, nullptr, pdbc,
                                           ML, 160, D_INNER, D_INNER, 0);
        // dt = softplus(dbc[:, :32] @ dtproj^T + b)  (4096 x 1024, K=32, lda=160)
        gemm3b<<<dim3(D_INNER / 128, ML / 128), 256>>>(pdbc, dtw_l, dtb_l, pdt,
                                                       ML, D_INNER, DT_RANK, 160, 1);
        transpose_k<<<tgrid, tblk>>>(pdt, pdtT, D_INNER, 0, L_);
        // selective scan (transposed operands) -> yT, then back to y
        scan2<<<(B_ * D_INNER) / 4, 128>>>(pdtT, pxcT, pzT, pdbc, Alog_l, Dp_l, pyT);
        transpose_k<<<tgrid, tblk>>>(pyT, py, L_, 0, D_INNER);
        // h = y @ out_w^T  (4096 x 512, K=1024)
        gemm3b<<<dim3(D_MODEL / 128, ML / 128), 256>>>(py, out_w_l, nullptr, ph,
                                                       ML, D_MODEL, D_INNER, D_INNER, 0);
    }

    fc_kernel<<<1, 384>>>(ph, fc_w, fc_b, out);
}

// round 10
// speedup vs baseline: 2.0744x; 1.0793x over previous
#include <cuda_runtime.h>
#include <cuda_bf16.h>
#include <stdint.h>
#include <math.h>

// ---------------- model dims ----------------
#define B_ 4
#define L_ 1024
#define D_IN 128
#define D_MODEL 512
#define N_LAYERS 2
#define N_CLASSES 3
#define D_INNER 1024
#define D_STATE 64
#define D_CONV 2
#define DT_RANK 32
#define ML (B_ * L_)

// ---------------- scratch (device globals; no allocation) ----------------
__device__ float g_h[ML * D_MODEL];
__device__ float g_xz[ML * 2 * D_INNER];
__device__ float g_xc[ML * D_INNER];
__device__ float g_dbc[ML * 160];
__device__ float g_y[ML * D_INNER];
// transposed views
__device__ float g_dtT[ML * D_INNER];   // [d][b*t]  (from GEMM directly)
__device__ float g_xcT[ML * D_INNER];   // [b][d][t]
__device__ float g_yT[ML * D_INNER];    // [b][d][t] (ungated)

__device__ __forceinline__ float softplus_f(float v) {
    return (v > 20.f) ? v : log1pf(__expf(v));
}
__device__ __forceinline__ void split2(float e0, float e1, unsigned int& hi, unsigned int& lo) {
    __nv_bfloat162 h = __floats2bfloat162_rn(e0, e1);
    float r0 = e0 - __bfloat162float(h.x);
    float r1 = e1 - __bfloat162float(h.y);
    __nv_bfloat162 l = __floats2bfloat162_rn(r0, r1);
    hi = *reinterpret_cast<unsigned int*>(&h);
    lo = *reinterpret_cast<unsigned int*>(&l);
}
__device__ __forceinline__ void mma_bf16(float* c, const unsigned int* a, const unsigned int* b) {
    asm volatile(
        "mma.sync.aligned.m16n8k16.row.col.f32.bf16.bf16.f32 "
        "{%0,%1,%2,%3}, {%4,%5,%6,%7}, {%8,%9}, {%0,%1,%2,%3};\n"
        : "+f"(c[0]), "+f"(c[1]), "+f"(c[2]), "+f"(c[3])
        : "r"(a[0]), "r"(a[1]), "r"(a[2]), "r"(a[3]),
          "r"(b[0]), "r"(b[1]));
}

// ---------------- split-bf16 (3-term) GEMM ----------------
// C(M,N) = A(M,K;lda) @ W(N,K;wlda)^T. act: 0 none, 1 bias[n]+softplus? (bias[n] add
// always when bias!=null, softplus if act==1), 2 = bias[m] + softplus (row bias).
#define SKW 20

__global__ __launch_bounds__(256, 2)
void gemm3b(const float* __restrict__ A, const float* __restrict__ W,
            const float* __restrict__ bias, float* __restrict__ C,
            int M, int N, int K, int lda, int wlda, int act)
{
    __shared__ unsigned int SH[2][4][128][SKW];

    const int tid = threadIdx.x;
    const int lane = tid & 31, w = tid >> 5;
    const int g = lane >> 2, l4 = lane & 3;
    const int wm = (w >> 2) * 64, wn = (w & 3) * 32;
    const int m0 = blockIdx.y * 128, n0 = blockIdx.x * 128;

    const int lrow = tid >> 1;
    const int lcolf = (tid & 1) * 16;
    const int p0 = lcolf >> 1;
    const float* Ag = A + (long)(m0 + lrow) * lda + lcolf;
    const int wrow = n0 + lrow;
    const float* Wg = W + (long)(wrow < N ? wrow : 0) * wlda + lcolf;

    float4 ra[4], rw[4];

    float acc[4][4][4];
#pragma unroll
    for (int i = 0; i < 4; i++)
#pragma unroll
        for (int j = 0; j < 4; j++)
#pragma unroll
            for (int e = 0; e < 4; e++) acc[i][j][e] = 0.f;

    const int niter = K / 32;

#pragma unroll
    for (int q = 0; q < 4; q++) {
        ra[q] = *(const float4*)(Ag + q * 4);
        rw[q] = *(const float4*)(Wg + q * 4);
    }
#pragma unroll
    for (int q = 0; q < 4; q++) {
        unsigned int h0, l0, h1, l1;
        split2(ra[q].x, ra[q].y, h0, l0);
        split2(ra[q].z, ra[q].w, h1, l1);
        SH[0][0][lrow][p0 + 2*q]     = h0;
        SH[0][0][lrow][p0 + 2*q + 1] = h1;
        SH[0][1][lrow][p0 + 2*q]     = l0;
        SH[0][1][lrow][p0 + 2*q + 1] = l1;
        split2(rw[q].x, rw[q].y, h0, l0);
        split2(rw[q].z, rw[q].w, h1, l1);
        SH[0][2][lrow][p0 + 2*q]     = h0;
        SH[0][2][lrow][p0 + 2*q + 1] = h1;
        SH[0][3][lrow][p0 + 2*q]     = l0;
        SH[0][3][lrow][p0 + 2*q + 1] = l1;
    }
    __syncthreads();

    for (int it = 0; it < niter; it++) {
        const int s = it & 1;
        if (it + 1 < niter) {
            const int k0 = (it + 1) * 32;
#pragma unroll
            for (int q = 0; q < 4; q++) {
                ra[q] = *(const float4*)(Ag + k0 + q * 4);
                rw[q] = *(const float4*)(Wg + k0 + q * 4);
            }
        }

#pragma unroll
        for (int ks = 0; ks < 2; ks++) {
            const int kb = ks * 8 + l4;
            unsigned int bh[4][2], bl[4][2];
#pragma unroll
            for (int j = 0; j < 4; j++) {
                const int r = wn + 8 * j + g;
                bh[j][0] = SH[s][2][r][kb];
                bh[j][1] = SH[s][2][r][kb + 4];
                bl[j][0] = SH[s][3][r][kb];
                bl[j][1] = SH[s][3][r][kb + 4];
            }
#pragma unroll
            for (int i = 0; i < 4; i++) {
                const int r0 = wm + 16 * i + g, r1 = r0 + 8;
                unsigned int ah[4], al[4];
                ah[0] = SH[s][0][r0][kb];     ah[1] = SH[s][0][r1][kb];
                ah[2] = SH[s][0][r0][kb + 4]; ah[3] = SH[s][0][r1][kb + 4];
                al[0] = SH[s][1][r0][kb];     al[1] = SH[s][1][r1][kb];
                al[2] = SH[s][1][r0][kb + 4]; al[3] = SH[s][1][r1][kb + 4];
#pragma unroll
                for (int j = 0; j < 4; j++) mma_bf16(acc[i][j], ah, bh[j]);
#pragma unroll
                for (int j = 0; j < 4; j++) mma_bf16(acc[i][j], ah, bl[j]);
#pragma unroll
                for (int j = 0; j < 4; j++) mma_bf16(acc[i][j], al, bh[j]);
            }
        }

        if (it + 1 < niter) {
            const int s2 = (it + 1) & 1;
#pragma unroll
            for (int q = 0; q < 4; q++) {
                unsigned int h0, l0, h1, l1;
                split2(ra[q].x, ra[q].y, h0, l0);
                split2(ra[q].z, ra[q].w, h1, l1);
                SH[s2][0][lrow][p0 + 2*q]     = h0;
                SH[s2][0][lrow][p0 + 2*q + 1] = h1;
                SH[s2][1][lrow][p0 + 2*q]     = l0;
                SH[s2][1][lrow][p0 + 2*q + 1] = l1;
                split2(rw[q].x, rw[q].y, h0, l0);
                split2(rw[q].z, rw[q].w, h1, l1);
                SH[s2][2][lrow][p0 + 2*q]     = h0;
                SH[s2][2][lrow][p0 + 2*q + 1] = h1;
                SH[s2][3][lrow][p0 + 2*q]     = l0;
                SH[s2][3][lrow][p0 + 2*q + 1] = l1;
            }
        }
        __syncthreads();
    }

#pragma unroll
    for (int i = 0; i < 4; i++) {
        const int mr0 = m0 + wm + 16 * i + g;
        const int mr1 = mr0 + 8;
        float rb0 = 0.f, rb1 = 0.f;
        if (act == 2) { rb0 = bias[mr0]; rb1 = bias[mr1]; }
#pragma unroll
        for (int j = 0; j < 4; j++) {
            const int n = n0 + wn + 8 * j + 2 * l4;
            if (n < N) {
                float v0 = acc[i][j][0], v1 = acc[i][j][1];
                float v2 = acc[i][j][2], v3 = acc[i][j][3];
                if (act == 2) {
                    v0 = softplus_f(v0 + rb0); v1 = softplus_f(v1 + rb0);
                    v2 = softplus_f(v2 + rb1); v3 = softplus_f(v3 + rb1);
                } else if (bias) {
                    float b0 = bias[n], b1 = bias[n + 1];
                    v0 += b0; v1 += b1; v2 += b0; v3 += b1;
                }
                *(float2*)(C + (long)mr0 * N + n) = make_float2(v0, v1);
                *(float2*)(C + (long)mr1 * N + n) = make_float2(v2, v3);
            }
        }
    }
}

// ---------------- conv + silu + transpose: writes xc [t][d] and xcT [b][d][t] ----
__global__ void conv_t(const float* __restrict__ xz,
                       const float* __restrict__ cw,
                       const float* __restrict__ cb,
                       float* __restrict__ xc, float* __restrict__ xcT)
{
    __shared__ float tile[32][33];
    const int b = blockIdx.z;
    const int t0 = blockIdx.y * 32;
    const int d0 = blockIdx.x * 32;
    const int tx = threadIdx.x, ty = threadIdx.y;
    const int d = d0 + tx;
    const float w0 = cw[d * 2 + 0], w1 = cw[d * 2 + 1], bsv = cb[d];
#pragma unroll
    for (int r = ty; r < 32; r += 8) {
        const int t = t0 + r;
        const long row = (long)(b * L_ + t) * (2 * D_INNER);
        float cur = xz[row + d];
        float prev = (t > 0) ? xz[row - 2 * D_INNER + d] : 0.f;
        float v = prev * w0 + cur * w1 + bsv;
        float sv = v / (1.f + __expf(-v));
        xc[(long)(b * L_ + t) * D_INNER + d] = sv;
        tile[r][tx] = sv;
    }
    __syncthreads();
#pragma unroll
    for (int r = ty; r < 32; r += 8)
        xcT[(long)(b * D_INNER + d0 + r) * L_ + t0 + tx] = tile[tx][r];
}

// ---------------- selective scan v3: no gating, dtT from GEMM layout ----------
__global__ __launch_bounds__(128)
void scan3(const float* __restrict__ dtT, const float* __restrict__ xcT,
           const float* __restrict__ dbc,
           const float* __restrict__ A_log, const float* __restrict__ Dp,
           float* __restrict__ yT)
{
    const int gw = (blockIdx.x * blockDim.x + threadIdx.x) >> 5;
    const int lane = threadIdx.x & 31;
    const int b = gw >> 10;
    const int d = gw & (D_INNER - 1);

    const float A0 = -__expf(A_log[d * D_STATE + 2 * lane]);
    const float A1 = -__expf(A_log[d * D_STATE + 2 * lane + 1]);
    const float Dd = Dp[d];

    const float* dtp = dtT + (long)d * ML + b * L_;        // [d][b*t]
    const float* xp  = xcT + ((long)b * D_INNER + d) * L_; // [b][d][t]
    const float* bcp = dbc + (long)b * L_ * 160 + DT_RANK + 2 * lane;
    float* yp = yT + ((long)b * D_INNER + d) * L_;

    float h0 = 0.f, h1 = 0.f;
    float4 d4 = *(const float4*)dtp;
    float4 x4 = *(const float4*)xp;
    float2 Bv = *(const float2*)bcp;
    float2 Cv = *(const float2*)(bcp + D_STATE);

    for (int t4 = 0; t4 < L_; t4 += 4) {
        const int tn = (t4 + 4 < L_) ? (t4 + 4) : t4;
        float4 d4n = *(const float4*)(dtp + tn);
        float4 x4n = *(const float4*)(xp + tn);
        float da[4], xa[4], ya[4];
        *(float4*)da = d4; *(float4*)xa = x4;
#pragma unroll
        for (int s = 0; s < 4; s++) {
            const int t = t4 + s;
            const int tp1 = (t + 1 < L_) ? (t + 1) : t;
            const float2 Bn = *(const float2*)(bcp + tp1 * 160);
            const float2 Cn = *(const float2*)(bcp + tp1 * 160 + D_STATE);
            const float dtv = da[s], xv = xa[s];
            const float u = dtv * xv;
            h0 = fmaf(h0, __expf(dtv * A0), u * Bv.x);
            h1 = fmaf(h1, __expf(dtv * A1), u * Bv.y);
            float p = h0 * Cv.x + h1 * Cv.y;
#pragma unroll
            for (int o = 16; o; o >>= 1) p += __shfl_xor_sync(0xffffffffu, p, o);
            ya[s] = p + xv * Dd;
            Bv = Bn; Cv = Cn;
        }
        if (lane == 0) *(float4*)(yp + t4) = *(const float4*)ya;
        d4 = d4n; x4 = x4n;
    }
}

// ---------------- gated transpose: y[t][d] = yT[b][d][t] * silu(z[t][d]) -------
__global__ void gate_t(const float* __restrict__ yT, const float* __restrict__ xz,
                       float* __restrict__ y)
{
    __shared__ float tile[32][33];
    const int b = blockIdx.z;
    const int t0 = blockIdx.y * 32;
    const int d0 = blockIdx.x * 32;
    const int tx = threadIdx.x, ty = threadIdx.y;
#pragma unroll
    for (int r = ty; r < 32; r += 8)
        tile[r][tx] = yT[(long)(b * D_INNER + d0 + r) * L_ + t0 + tx];
    __syncthreads();
#pragma unroll
    for (int r = ty; r < 32; r += 8) {
        const int t = t0 + r, d = d0 + tx;
        const float zv = xz[(long)(b * L_ + t) * (2 * D_INNER) + D_INNER + d];
        y[(long)(b * L_ + t) * D_INNER + d] = tile[tx][r] * (zv / (1.f + __expf(-zv)));
    }
}

// ---------------- final FC ----------------
__global__ void fc_kernel(const float* __restrict__ h, const float* __restrict__ fc_w,
                          const float* __restrict__ fc_b, float* __restrict__ out)
{
    const int w = threadIdx.x >> 5;
    const int lane = threadIdx.x & 31;
    if (w >= B_ * N_CLASSES) return;
    const int b = w / N_CLASSES, c = w % N_CLASSES;
    const float* hp = h + (long)(b * L_ + (L_ - 1)) * D_MODEL;
    float s = 0.f;
    for (int k = lane; k < D_MODEL; k += 32) s += hp[k] * fc_w[c * D_MODEL + k];
#pragma unroll
    for (int o = 16; o; o >>= 1) s += __shfl_xor_sync(0xffffffffu, s, o);
    if (lane == 0) out[b * N_CLASSES + c] = s + fc_b[c];
}

// ---------------- launch ----------------
extern "C" void kernel_launch(void* const* d_in, const int* in_sizes, int n_in,
                              void* d_out, int out_size)
{
    const float* x        = (const float*)d_in[0];
    const float* exp_w    = (const float*)d_in[1];
    const float* exp_b    = (const float*)d_in[2];
    const float* in_w     = (const float*)d_in[3];
    const float* conv_w   = (const float*)d_in[4];
    const float* conv_b   = (const float*)d_in[5];
    const float* xproj_w  = (const float*)d_in[6];
    const float* dtproj_w = (const float*)d_in[7];
    const float* dtproj_b = (const float*)d_in[8];
    const float* A_log    = (const float*)d_in[9];
    const float* Dp       = (const float*)d_in[10];
    const float* out_w    = (const float*)d_in[11];
    const float* fc_w     = (const float*)d_in[12];
    const float* fc_b     = (const float*)d_in[13];
    float* out = (float*)d_out;

    float *ph, *pxz, *pxc, *pdbc, *py, *pdtT, *pxcT, *pyT;
    cudaGetSymbolAddress((void**)&ph,   g_h);
    cudaGetSymbolAddress((void**)&pxz,  g_xz);
    cudaGetSymbolAddress((void**)&pxc,  g_xc);
    cudaGetSymbolAddress((void**)&pdbc, g_dbc);
    cudaGetSymbolAddress((void**)&py,   g_y);
    cudaGetSymbolAddress((void**)&pdtT, g_dtT);
    cudaGetSymbolAddress((void**)&pxcT, g_xcT);
    cudaGetSymbolAddress((void**)&pyT,  g_yT);

    const dim3 tgrid(32, 32, 4), tblk(32, 8);

    // embed: h = x @ exp_w^T + exp_b   (4096 x 512, K=128)
    gemm3b<<<dim3(D_MODEL / 128, ML / 128), 256>>>(x, exp_w, exp_b, ph,
                                                   ML, D_MODEL, D_IN, D_IN, D_IN, 0);

    for (int l = 0; l < N_LAYERS; l++) {
        const float* in_w_l   = in_w     + (long)l * 2 * D_INNER * D_MODEL;
        const float* conv_w_l = conv_w   + (long)l * D_INNER * D_CONV;
        const float* conv_b_l = conv_b   + (long)l * D_INNER;
        const float* xproj_l  = xproj_w  + (long)l * 160 * D_INNER;
        const float* dtw_l    = dtproj_w + (long)l * D_INNER * DT_RANK;
        const float* dtb_l    = dtproj_b + (long)l * D_INNER;
        const float* Alog_l   = A_log    + (long)l * D_INNER * D_STATE;
        const float* Dp_l     = Dp       + (long)l * D_INNER;
        const float* out_w_l  = out_w    + (long)l * D_MODEL * D_INNER;

        // xz = h @ in_w^T   (4096 x 2048, K=512)
        gemm3b<<<dim3(2 * D_INNER / 128, ML / 128), 256>>>(
            ph, in_w_l, nullptr, pxz, ML, 2 * D_INNER, D_MODEL, D_MODEL, D_MODEL, 0);
        // conv + silu + transpose -> xc, xcT
        conv_t<<<tgrid, tblk>>>(pxz, conv_w_l, conv_b_l, pxc, pxcT);
        // dbc = xc @ xproj^T  (4096 x 160, K=1024)
        gemm3b<<<dim3(2, ML / 128), 256>>>(
            pxc, xproj_l, nullptr, pdbc, ML, 160, D_INNER, D_INNER, D_INNER, 0);
        // dtT = softplus(dtproj_w @ dbc[:, :32]^T + b[d])  -> [d][b*t] directly
        // A = dtproj_w (1024 x 32), W = dbc rows (4096 x 32, wlda=160)
        gemm3b<<<dim3(ML / 128, D_INNER / 128), 256>>>(
            dtw_l, pdbc, dtb_l, pdtT, D_INNER, ML, DT_RANK, DT_RANK, 160, 2);
        // selective scan -> yT (ungated)
        scan3<<<(B_ * D_INNER) / 4, 128>>>(pdtT, pxcT, pdbc, Alog_l, Dp_l, pyT);
        // gate + transpose back -> y [t][d]
        gate_t<<<tgrid, tblk>>>(pyT, pxz, py);
        // h = y @ out_w^T  (4096 x 512, K=1024)
        gemm3b<<<dim3(D_MODEL / 128, ML / 128), 256>>>(
            py, out_w_l, nullptr, ph, ML, D_MODEL, D_INNER, D_INNER, D_INNER, 0);
    }

    fc_kernel<<<1, 384>>>(ph, fc_w, fc_b, out);
}

// round 12
// speedup vs baseline: 2.2165x; 1.0685x over previous
#include <cuda_runtime.h>
#include <cuda_bf16.h>
#include <stdint.h>
#include <math.h>

// ---------------- model dims ----------------
#define B_ 4
#define L_ 1024
#define D_IN 128
#define D_MODEL 512
#define N_LAYERS 2
#define N_CLASSES 3
#define D_INNER 1024
#define D_STATE 64
#define D_CONV 2
#define DT_RANK 32
#define ML (B_ * L_)

// ---------------- scratch (device globals; no allocation) ----------------
__device__ float g_h[ML * D_MODEL];
__device__ float g_xz[ML * 2 * D_INNER];
__device__ float g_xc[ML * D_INNER];
__device__ float g_dbc[ML * 160];
__device__ float g_y[ML * D_INNER];
__device__ float g_dtT[ML * D_INNER];   // [d][b*t]
__device__ float g_xcT[ML * D_INNER];   // [b][d][t]
__device__ float g_yT[ML * D_INNER];    // [b][d][t]

__device__ __forceinline__ float softplus_f(float v) {
    return (v > 20.f) ? v : log1pf(__expf(v));
}
__device__ __forceinline__ void split2(float e0, float e1, unsigned int& hi, unsigned int& lo) {
    __nv_bfloat162 h = __floats2bfloat162_rn(e0, e1);
    float r0 = e0 - __bfloat162float(h.x);
    float r1 = e1 - __bfloat162float(h.y);
    __nv_bfloat162 l = __floats2bfloat162_rn(r0, r1);
    hi = *reinterpret_cast<unsigned int*>(&h);
    lo = *reinterpret_cast<unsigned int*>(&l);
}
__device__ __forceinline__ void mma_bf16(float* c, const unsigned int* a, const unsigned int* b) {
    asm volatile(
        "mma.sync.aligned.m16n8k16.row.col.f32.bf16.bf16.f32 "
        "{%0,%1,%2,%3}, {%4,%5,%6,%7}, {%8,%9}, {%0,%1,%2,%3};\n"
        : "+f"(c[0]), "+f"(c[1]), "+f"(c[2]), "+f"(c[3])
        : "r"(a[0]), "r"(a[1]), "r"(a[2]), "r"(a[3]),
          "r"(b[0]), "r"(b[1]));
}

// ---------------- split-bf16 (3-term) GEMM ----------------
// C(M,N) (+)= A(M,K;lda) @ W(N,K;wlda)^T for K-chunk blockIdx.z (chunk size = K arg).
// act: 0 plain (+bias[n] if bias), 2 = bias[m]+softplus, 3 = atomicAdd accumulate.
#define SKW 20

__global__ __launch_bounds__(256, 2)
void gemm3b(const float* __restrict__ A, const float* __restrict__ W,
            const float* __restrict__ bias, float* __restrict__ C,
            int M, int N, int K, int lda, int wlda, int act)
{
    __shared__ unsigned int SH[2][4][128][SKW];

    const int tid = threadIdx.x;
    const int lane = tid & 31, w = tid >> 5;
    const int g = lane >> 2, l4 = lane & 3;
    const int wm = (w >> 2) * 64, wn = (w & 3) * 32;
    const int m0 = blockIdx.y * 128, n0 = blockIdx.x * 128;
    const int koff = blockIdx.z * K;

    const int lrow = tid >> 1;
    const int lcolf = (tid & 1) * 16;
    const int p0 = lcolf >> 1;
    const float* Ag = A + (long)(m0 + lrow) * lda + lcolf + koff;
    const int wrow = n0 + lrow;
    const float* Wg = W + (long)(wrow < N ? wrow : 0) * wlda + lcolf + koff;

    float4 ra[4], rw[4];

    float acc[4][4][4];
#pragma unroll
    for (int i = 0; i < 4; i++)
#pragma unroll
        for (int j = 0; j < 4; j++)
#pragma unroll
            for (int e = 0; e < 4; e++) acc[i][j][e] = 0.f;

    const int niter = K / 32;

#pragma unroll
    for (int q = 0; q < 4; q++) {
        ra[q] = *(const float4*)(Ag + q * 4);
        rw[q] = *(const float4*)(Wg + q * 4);
    }
#pragma unroll
    for (int q = 0; q < 4; q++) {
        unsigned int h0, l0, h1, l1;
        split2(ra[q].x, ra[q].y, h0, l0);
        split2(ra[q].z, ra[q].w, h1, l1);
        SH[0][0][lrow][p0 + 2*q]     = h0;
        SH[0][0][lrow][p0 + 2*q + 1] = h1;
        SH[0][1][lrow][p0 + 2*q]     = l0;
        SH[0][1][lrow][p0 + 2*q + 1] = l1;
        split2(rw[q].x, rw[q].y, h0, l0);
        split2(rw[q].z, rw[q].w, h1, l1);
        SH[0][2][lrow][p0 + 2*q]     = h0;
        SH[0][2][lrow][p0 + 2*q + 1] = h1;
        SH[0][3][lrow][p0 + 2*q]     = l0;
        SH[0][3][lrow][p0 + 2*q + 1] = l1;
    }
    __syncthreads();

    for (int it = 0; it < niter; it++) {
        const int s = it & 1;
        if (it + 1 < niter) {
            const int k0 = (it + 1) * 32;
#pragma unroll
            for (int q = 0; q < 4; q++) {
                ra[q] = *(const float4*)(Ag + k0 + q * 4);
                rw[q] = *(const float4*)(Wg + k0 + q * 4);
            }
        }

#pragma unroll
        for (int ks = 0; ks < 2; ks++) {
            const int kb = ks * 8 + l4;
            unsigned int bh[4][2], bl[4][2];
#pragma unroll
            for (int j = 0; j < 4; j++) {
                const int r = wn + 8 * j + g;
                bh[j][0] = SH[s][2][r][kb];
                bh[j][1] = SH[s][2][r][kb + 4];
                bl[j][0] = SH[s][3][r][kb];
                bl[j][1] = SH[s][3][r][kb + 4];
            }
#pragma unroll
            for (int i = 0; i < 4; i++) {
                const int r0 = wm + 16 * i + g, r1 = r0 + 8;
                unsigned int ah[4], al[4];
                ah[0] = SH[s][0][r0][kb];     ah[1] = SH[s][0][r1][kb];
                ah[2] = SH[s][0][r0][kb + 4]; ah[3] = SH[s][0][r1][kb + 4];
                al[0] = SH[s][1][r0][kb];     al[1] = SH[s][1][r1][kb];
                al[2] = SH[s][1][r0][kb + 4]; al[3] = SH[s][1][r1][kb + 4];
#pragma unroll
                for (int j = 0; j < 4; j++) mma_bf16(acc[i][j], ah, bh[j]);
#pragma unroll
                for (int j = 0; j < 4; j++) mma_bf16(acc[i][j], ah, bl[j]);
#pragma unroll
                for (int j = 0; j < 4; j++) mma_bf16(acc[i][j], al, bh[j]);
            }
        }

        if (it + 1 < niter) {
            const int s2 = (it + 1) & 1;
#pragma unroll
            for (int q = 0; q < 4; q++) {
                unsigned int h0, l0, h1, l1;
                split2(ra[q].x, ra[q].y, h0, l0);
                split2(ra[q].z, ra[q].w, h1, l1);
                SH[s2][0][lrow][p0 + 2*q]     = h0;
                SH[s2][0][lrow][p0 + 2*q + 1] = h1;
                SH[s2][1][lrow][p0 + 2*q]     = l0;
                SH[s2][1][lrow][p0 + 2*q + 1] = l1;
                split2(rw[q].x, rw[q].y, h0, l0);
                split2(rw[q].z, rw[q].w, h1, l1);
                SH[s2][2][lrow][p0 + 2*q]     = h0;
                SH[s2][2][lrow][p0 + 2*q + 1] = h1;
                SH[s2][3][lrow][p0 + 2*q]     = l0;
                SH[s2][3][lrow][p0 + 2*q + 1] = l1;
            }
        }
        __syncthreads();
    }

#pragma unroll
    for (int i = 0; i < 4; i++) {
        const int mr0 = m0 + wm + 16 * i + g;
        const int mr1 = mr0 + 8;
        float rb0 = 0.f, rb1 = 0.f;
        if (act == 2) { rb0 = bias[mr0]; rb1 = bias[mr1]; }
#pragma unroll
        for (int j = 0; j < 4; j++) {
            const int n = n0 + wn + 8 * j + 2 * l4;
            if (n < N) {
                float v0 = acc[i][j][0], v1 = acc[i][j][1];
                float v2 = acc[i][j][2], v3 = acc[i][j][3];
                if (act == 3) {
                    atomicAdd(C + (long)mr0 * N + n,     v0);
                    atomicAdd(C + (long)mr0 * N + n + 1, v1);
                    atomicAdd(C + (long)mr1 * N + n,     v2);
                    atomicAdd(C + (long)mr1 * N + n + 1, v3);
                } else {
                    if (act == 2) {
                        v0 = softplus_f(v0 + rb0); v1 = softplus_f(v1 + rb0);
                        v2 = softplus_f(v2 + rb1); v3 = softplus_f(v3 + rb1);
                    } else if (bias) {
                        float b0 = bias[n], b1 = bias[n + 1];
                        v0 += b0; v1 += b1; v2 += b0; v3 += b1;
                    }
                    *(float2*)(C + (long)mr0 * N + n) = make_float2(v0, v1);
                    *(float2*)(C + (long)mr1 * N + n) = make_float2(v2, v3);
                }
            }
        }
    }
}

// ---------------- conv + silu + transpose ----------------
__global__ void conv_t(const float* __restrict__ xz,
                       const float* __restrict__ cw,
                       const float* __restrict__ cb,
                       float* __restrict__ xc, float* __restrict__ xcT)
{
    __shared__ float tile[32][33];
    const int b = blockIdx.z;
    const int t0 = blockIdx.y * 32;
    const int d0 = blockIdx.x * 32;
    const int tx = threadIdx.x, ty = threadIdx.y;
    const int d = d0 + tx;
    const float w0 = cw[d * 2 + 0], w1 = cw[d * 2 + 1], bsv = cb[d];
#pragma unroll
    for (int r = ty; r < 32; r += 8) {
        const int t = t0 + r;
        const long row = (long)(b * L_ + t) * (2 * D_INNER);
        float cur = xz[row + d];
        float prev = (t > 0) ? xz[row - 2 * D_INNER + d] : 0.f;
        float v = prev * w0 + cur * w1 + bsv;
        float sv = v / (1.f + __expf(-v));
        xc[(long)(b * L_ + t) * D_INNER + d] = sv;
        tile[r][tx] = sv;
    }
    __syncthreads();
#pragma unroll
    for (int r = ty; r < 32; r += 8)
        xcT[(long)(b * D_INNER + d0 + r) * L_ + t0 + tx] = tile[tx][r];
}

// ---------------- selective scan ----------------
__global__ __launch_bounds__(128)
void scan3(const float* __restrict__ dtT, const float* __restrict__ xcT,
           const float* __restrict__ dbc,
           const float* __restrict__ A_log, const float* __restrict__ Dp,
           float* __restrict__ yT)
{
    const int gw = (blockIdx.x * blockDim.x + threadIdx.x) >> 5;
    const int lane = threadIdx.x & 31;
    const int b = gw >> 10;
    const int d = gw & (D_INNER - 1);

    const float A0 = -__expf(A_log[d * D_STATE + 2 * lane]);
    const float A1 = -__expf(A_log[d * D_STATE + 2 * lane + 1]);
    const float Dd = Dp[d];

    const float* dtp = dtT + (long)d * ML + b * L_;
    const float* xp  = xcT + ((long)b * D_INNER + d) * L_;
    const float* bcp = dbc + (long)b * L_ * 160 + DT_RANK + 2 * lane;
    float* yp = yT + ((long)b * D_INNER + d) * L_;

    float h0 = 0.f, h1 = 0.f;
    float4 d4 = *(const float4*)dtp;
    float4 x4 = *(const float4*)xp;
    float2 Bv = *(const float2*)bcp;
    float2 Cv = *(const float2*)(bcp + D_STATE);

    for (int t4 = 0; t4 < L_; t4 += 4) {
        const int tn = (t4 + 4 < L_) ? (t4 + 4) : t4;
        float4 d4n = *(const float4*)(dtp + tn);
        float4 x4n = *(const float4*)(xp + tn);
        float da[4], xa[4], ya[4];
        *(float4*)da = d4; *(float4*)xa = x4;
#pragma unroll
        for (int s = 0; s < 4; s++) {
            const int t = t4 + s;
            const int tp1 = (t + 1 < L_) ? (t + 1) : t;
            const float2 Bn = *(const float2*)(bcp + tp1 * 160);
            const float2 Cn = *(const float2*)(bcp + tp1 * 160 + D_STATE);
            const float dtv = da[s], xv = xa[s];
            const float u = dtv * xv;
            h0 = fmaf(h0, __expf(dtv * A0), u * Bv.x);
            h1 = fmaf(h1, __expf(dtv * A1), u * Bv.y);
            float p = h0 * Cv.x + h1 * Cv.y;
#pragma unroll
            for (int o = 16; o; o >>= 1) p += __shfl_xor_sync(0xffffffffu, p, o);
            ya[s] = p + xv * Dd;
            Bv = Bn; Cv = Cn;
        }
        if (lane == 0) *(float4*)(yp + t4) = *(const float4*)ya;
        d4 = d4n; x4 = x4n;
    }
}

// ---------------- gated transpose ----------------
__global__ void gate_t(const float* __restrict__ yT, const float* __restrict__ xz,
                       float* __restrict__ y)
{
    __shared__ float tile[32][33];
    const int b = blockIdx.z;
    const int t0 = blockIdx.y * 32;
    const int d0 = blockIdx.x * 32;
    const int tx = threadIdx.x, ty = threadIdx.y;
#pragma unroll
    for (int r = ty; r < 32; r += 8)
        tile[r][tx] = yT[(long)(b * D_INNER + d0 + r) * L_ + t0 + tx];
    __syncthreads();
#pragma unroll
    for (int r = ty; r < 32; r += 8) {
        const int t = t0 + r, d = d0 + tx;
        const float zv = xz[(long)(b * L_ + t) * (2 * D_INNER) + D_INNER + d];
        y[(long)(b * L_ + t) * D_INNER + d] = tile[tx][r] * (zv / (1.f + __expf(-zv)));
    }
}

// ---------------- final FC ----------------
__global__ void fc_kernel(const float* __restrict__ h, const float* __restrict__ fc_w,
                          const float* __restrict__ fc_b, float* __restrict__ out)
{
    const int w = threadIdx.x >> 5;
    const int lane = threadIdx.x & 31;
    if (w >= B_ * N_CLASSES) return;
    const int b = w / N_CLASSES, c = w % N_CLASSES;
    const float* hp = h + (long)(b * L_ + (L_ - 1)) * D_MODEL;
    float s = 0.f;
    for (int k = lane; k < D_MODEL; k += 32) s += hp[k] * fc_w[c * D_MODEL + k];
#pragma unroll
    for (int o = 16; o; o >>= 1) s += __shfl_xor_sync(0xffffffffu, s, o);
    if (lane == 0) out[b * N_CLASSES + c] = s + fc_b[c];
}

// ---------------- launch ----------------
extern "C" void kernel_launch(void* const* d_in, const int* in_sizes, int n_in,
                              void* d_out, int out_size)
{
    const float* x        = (const float*)d_in[0];
    const float* exp_w    = (const float*)d_in[1];
    const float* exp_b    = (const float*)d_in[2];
    const float* in_w     = (const float*)d_in[3];
    const float* conv_w   = (const float*)d_in[4];
    const float* conv_b   = (const float*)d_in[5];
    const float* xproj_w  = (const float*)d_in[6];
    const float* dtproj_w = (const float*)d_in[7];
    const float* dtproj_b = (const float*)d_in[8];
    const float* A_log    = (const float*)d_in[9];
    const float* Dp       = (const float*)d_in[10];
    const float* out_w    = (const float*)d_in[11];
    const float* fc_w     = (const float*)d_in[12];
    const float* fc_b     = (const float*)d_in[13];
    float* out = (float*)d_out;

    float *ph, *pxz, *pxc, *pdbc, *py, *pdtT, *pxcT, *pyT;
    cudaGetSymbolAddress((void**)&ph,   g_h);
    cudaGetSymbolAddress((void**)&pxz,  g_xz);
    cudaGetSymbolAddress((void**)&pxc,  g_xc);
    cudaGetSymbolAddress((void**)&pdbc, g_dbc);
    cudaGetSymbolAddress((void**)&py,   g_y);
    cudaGetSymbolAddress((void**)&pdtT, g_dtT);
    cudaGetSymbolAddress((void**)&pxcT, g_xcT);
    cudaGetSymbolAddress((void**)&pyT,  g_yT);

    const dim3 tgrid(32, 32, 4), tblk(32, 8);

    // embed: h = x @ exp_w^T + exp_b   (4096 x 512, K=128)
    gemm3b<<<dim3(D_MODEL / 128, ML / 128), 256>>>(x, exp_w, exp_b, ph,
                                                   ML, D_MODEL, D_IN, D_IN, D_IN, 0);

    for (int l = 0; l < N_LAYERS; l++) {
        const float* in_w_l   = in_w     + (long)l * 2 * D_INNER * D_MODEL;
        const float* conv_w_l = conv_w   + (long)l * D_INNER * D_CONV;
        const float* conv_b_l = conv_b   + (long)l * D_INNER;
        const float* xproj_l  = xproj_w  + (long)l * 160 * D_INNER;
        const float* dtw_l    = dtproj_w + (long)l * D_INNER * DT_RANK;
        const float* dtb_l    = dtproj_b + (long)l * D_INNER;
        const float* Alog_l   = A_log    + (long)l * D_INNER * D_STATE;
        const float* Dp_l     = Dp       + (long)l * D_INNER;
        const float* out_w_l  = out_w    + (long)l * D_MODEL * D_INNER;

        // xz = h @ in_w^T   (4096 x 2048, K=512)
        gemm3b<<<dim3(2 * D_INNER / 128, ML / 128), 256>>>(
            ph, in_w_l, nullptr, pxz, ML, 2 * D_INNER, D_MODEL, D_MODEL, D_MODEL, 0);
        // conv + silu + transpose -> xc, xcT
        conv_t<<<tgrid, tblk>>>(pxz, conv_w_l, conv_b_l, pxc, pxcT);
        // dbc = xc @ xproj^T  (4096 x 160, K=1024) — split-K x4, atomic accumulate
        cudaMemsetAsync(pdbc, 0, (size_t)ML * 160 * sizeof(float));
        gemm3b<<<dim3(2, ML / 128, 4), 256>>>(
            pxc, xproj_l, nullptr, pdbc, ML, 160, 256, D_INNER, D_INNER, 3);
        // dtT = softplus(dtproj_w @ dbc[:, :32]^T + b[d])  -> [d][b*t]
        gemm3b<<<dim3(ML / 128, D_INNER / 128), 256>>>(
            dtw_l, pdbc, dtb_l, pdtT, D_INNER, ML, DT_RANK, DT_RANK, 160, 2);
        // selective scan -> yT (ungated)
        scan3<<<(B_ * D_INNER) / 4, 128>>>(pdtT, pxcT, pdbc, Alog_l, Dp_l, pyT);
        // gate + transpose back -> y [t][d]
        gate_t<<<tgrid, tblk>>>(pyT, pxz, py);
        // h = y @ out_w^T  (4096 x 512, K=1024) — split-K x2, atomic accumulate
        cudaMemsetAsync(ph, 0, (size_t)ML * D_MODEL * sizeof(float));
        gemm3b<<<dim3(D_MODEL / 128, ML / 128, 2), 256>>>(
            py, out_w_l, nullptr, ph, ML, D_MODEL, 512, D_INNER, D_INNER, 3);
    }

    fc_kernel<<<1, 384>>>(ph, fc_w, fc_b, out);
}

// round 14
// speedup vs baseline: 2.5535x; 1.1520x over previous
#include <cuda_runtime.h>
#include <cuda_bf16.h>
#include <stdint.h>
#include <math.h>

// ---------------- model dims ----------------
#define B_ 4
#define L_ 1024
#define D_IN 128
#define D_MODEL 512
#define N_LAYERS 2
#define N_CLASSES 3
#define D_INNER 1024
#define D_STATE 64
#define D_CONV 2
#define DT_RANK 32
#define ML (B_ * L_)

// ---------------- scratch (device globals; no allocation) ----------------
__device__ float g_h[ML * D_MODEL];
__device__ float g_h2[ML * D_MODEL];    // second K-slice of out-proj
__device__ float g_xz[ML * 2 * D_INNER];
__device__ float g_xc[ML * D_INNER];
__device__ float g_dbc[ML * 160];
__device__ float g_y[ML * D_INNER];
__device__ float g_dtT[ML * D_INNER];   // [d][b*t]
__device__ float g_xcT[ML * D_INNER];   // [b][d][t]
__device__ float g_yT[ML * D_INNER];    // [b][d][t]

__device__ __forceinline__ float softplus_f(float v) {
    return (v > 20.f) ? v : log1pf(__expf(v));
}
__device__ __forceinline__ void split2(float e0, float e1, unsigned int& hi, unsigned int& lo) {
    __nv_bfloat162 h = __floats2bfloat162_rn(e0, e1);
    float r0 = e0 - __bfloat162float(h.x);
    float r1 = e1 - __bfloat162float(h.y);
    __nv_bfloat162 l = __floats2bfloat162_rn(r0, r1);
    hi = *reinterpret_cast<unsigned int*>(&h);
    lo = *reinterpret_cast<unsigned int*>(&l);
}
__device__ __forceinline__ void mma_bf16(float* c, const unsigned int* a, const unsigned int* b) {
    asm volatile(
        "mma.sync.aligned.m16n8k16.row.col.f32.bf16.bf16.f32 "
        "{%0,%1,%2,%3}, {%4,%5,%6,%7}, {%8,%9}, {%0,%1,%2,%3};\n"
        : "+f"(c[0]), "+f"(c[1]), "+f"(c[2]), "+f"(c[3])
        : "r"(a[0]), "r"(a[1]), "r"(a[2]), "r"(a[3]),
          "r"(b[0]), "r"(b[1]));
}

// ---------------- split-bf16 (3-term) GEMM ----------------
// C = (A [+A2])(M,K;lda) @ W(N,K;wlda)^T for K-chunk blockIdx.z.
// act: 0 plain (+bias[n] if bias), 2 = bias[m]+softplus, 3 = atomicAdd,
//      4 = slice store: blockIdx.z==0 -> C, ==1 -> C2 (no bias).
#define SKW 20

template<int TAG>
__global__ __launch_bounds__(256, 2)
void gemm3b(const float* __restrict__ A, const float* __restrict__ A2,
            const float* __restrict__ W,
            const float* __restrict__ bias, float* __restrict__ C,
            float* __restrict__ C2,
            int M, int N, int K, int lda, int wlda, int act)
{
    __shared__ unsigned int SH[2][4][128][SKW];

    const int tid = threadIdx.x;
    const int lane = tid & 31, w = tid >> 5;
    const int g = lane >> 2, l4 = lane & 3;
    const int wm = (w >> 2) * 64, wn = (w & 3) * 32;
    const int m0 = blockIdx.y * 128, n0 = blockIdx.x * 128;
    const int koff = blockIdx.z * K;

    const int lrow = tid >> 1;
    const int lcolf = (tid & 1) * 16;
    const int p0 = lcolf >> 1;
    const float* Ag = A + (long)(m0 + lrow) * lda + lcolf + koff;
    const float* Ag2 = A2 ? A2 + (long)(m0 + lrow) * lda + lcolf + koff : nullptr;
    const int wrow = n0 + lrow;
    const float* Wg = W + (long)(wrow < N ? wrow : 0) * wlda + lcolf + koff;

    float4 ra[4], rw[4];

    float acc[4][4][4];
#pragma unroll
    for (int i = 0; i < 4; i++)
#pragma unroll
        for (int j = 0; j < 4; j++)
#pragma unroll
            for (int e = 0; e < 4; e++) acc[i][j][e] = 0.f;

    const int niter = K / 32;

#pragma unroll
    for (int q = 0; q < 4; q++) {
        ra[q] = *(const float4*)(Ag + q * 4);
        if (Ag2) {
            float4 t = *(const float4*)(Ag2 + q * 4);
            ra[q].x += t.x; ra[q].y += t.y; ra[q].z += t.z; ra[q].w += t.w;
        }
        rw[q] = *(const float4*)(Wg + q * 4);
    }
#pragma unroll
    for (int q = 0; q < 4; q++) {
        unsigned int h0, l0, h1, l1;
        split2(ra[q].x, ra[q].y, h0, l0);
        split2(ra[q].z, ra[q].w, h1, l1);
        SH[0][0][lrow][p0 + 2*q]     = h0;
        SH[0][0][lrow][p0 + 2*q + 1] = h1;
        SH[0][1][lrow][p0 + 2*q]     = l0;
        SH[0][1][lrow][p0 + 2*q + 1] = l1;
        split2(rw[q].x, rw[q].y, h0, l0);
        split2(rw[q].z, rw[q].w, h1, l1);
        SH[0][2][lrow][p0 + 2*q]     = h0;
        SH[0][2][lrow][p0 + 2*q + 1] = h1;
        SH[0][3][lrow][p0 + 2*q]     = l0;
        SH[0][3][lrow][p0 + 2*q + 1] = l1;
    }
    __syncthreads();

    for (int it = 0; it < niter; it++) {
        const int s = it & 1;
        if (it + 1 < niter) {
            const int k0 = (it + 1) * 32;
#pragma unroll
            for (int q = 0; q < 4; q++) {
                ra[q] = *(const float4*)(Ag + k0 + q * 4);
                if (Ag2) {
                    float4 t = *(const float4*)(Ag2 + k0 + q * 4);
                    ra[q].x += t.x; ra[q].y += t.y; ra[q].z += t.z; ra[q].w += t.w;
                }
                rw[q] = *(const float4*)(Wg + k0 + q * 4);
            }
        }

#pragma unroll
        for (int ks = 0; ks < 2; ks++) {
            const int kb = ks * 8 + l4;
            unsigned int bh[4][2], bl[4][2];
#pragma unroll
            for (int j = 0; j < 4; j++) {
                const int r = wn + 8 * j + g;
                bh[j][0] = SH[s][2][r][kb];
                bh[j][1] = SH[s][2][r][kb + 4];
                bl[j][0] = SH[s][3][r][kb];
                bl[j][1] = SH[s][3][r][kb + 4];
            }
#pragma unroll
            for (int i = 0; i < 4; i++) {
                const int r0 = wm + 16 * i + g, r1 = r0 + 8;
                unsigned int ah[4], al[4];
                ah[0] = SH[s][0][r0][kb];     ah[1] = SH[s][0][r1][kb];
                ah[2] = SH[s][0][r0][kb + 4]; ah[3] = SH[s][0][r1][kb + 4];
                al[0] = SH[s][1][r0][kb];     al[1] = SH[s][1][r1][kb];
                al[2] = SH[s][1][r0][kb + 4]; al[3] = SH[s][1][r1][kb + 4];
#pragma unroll
                for (int j = 0; j < 4; j++) mma_bf16(acc[i][j], ah, bh[j]);
#pragma unroll
                for (int j = 0; j < 4; j++) mma_bf16(acc[i][j], ah, bl[j]);
#pragma unroll
                for (int j = 0; j < 4; j++) mma_bf16(acc[i][j], al, bh[j]);
            }
        }

        if (it + 1 < niter) {
            const int s2 = (it + 1) & 1;
#pragma unroll
            for (int q = 0; q < 4; q++) {
                unsigned int h0, l0, h1, l1;
                split2(ra[q].x, ra[q].y, h0, l0);
                split2(ra[q].z, ra[q].w, h1, l1);
                SH[s2][0][lrow][p0 + 2*q]     = h0;
                SH[s2][0][lrow][p0 + 2*q + 1] = h1;
                SH[s2][1][lrow][p0 + 2*q]     = l0;
                SH[s2][1][lrow][p0 + 2*q + 1] = l1;
                split2(rw[q].x, rw[q].y, h0, l0);
                split2(rw[q].z, rw[q].w, h1, l1);
                SH[s2][2][lrow][p0 + 2*q]     = h0;
                SH[s2][2][lrow][p0 + 2*q + 1] = h1;
                SH[s2][3][lrow][p0 + 2*q]     = l0;
                SH[s2][3][lrow][p0 + 2*q + 1] = l1;
            }
        }
        __syncthreads();
    }

    float* Cout = (act == 4 && blockIdx.z == 1) ? C2 : C;
#pragma unroll
    for (int i = 0; i < 4; i++) {
        const int mr0 = m0 + wm + 16 * i + g;
        const int mr1 = mr0 + 8;
        float rb0 = 0.f, rb1 = 0.f;
        if (act == 2) { rb0 = bias[mr0]; rb1 = bias[mr1]; }
#pragma unroll
        for (int j = 0; j < 4; j++) {
            const int n = n0 + wn + 8 * j + 2 * l4;
            if (n < N) {
                float v0 = acc[i][j][0], v1 = acc[i][j][1];
                float v2 = acc[i][j][2], v3 = acc[i][j][3];
                if (act == 3) {
                    atomicAdd(C + (long)mr0 * N + n,     v0);
                    atomicAdd(C + (long)mr0 * N + n + 1, v1);
                    atomicAdd(C + (long)mr1 * N + n,     v2);
                    atomicAdd(C + (long)mr1 * N + n + 1, v3);
                } else {
                    if (act == 2) {
                        v0 = softplus_f(v0 + rb0); v1 = softplus_f(v1 + rb0);
                        v2 = softplus_f(v2 + rb1); v3 = softplus_f(v3 + rb1);
                    } else if (act == 0 && bias) {
                        float b0 = bias[n], b1 = bias[n + 1];
                        v0 += b0; v1 += b1; v2 += b0; v3 += b1;
                    }
                    *(float2*)(Cout + (long)mr0 * N + n) = make_float2(v0, v1);
                    *(float2*)(Cout + (long)mr1 * N + n) = make_float2(v2, v3);
                }
            }
        }
    }
}

// ---------------- conv + silu + transpose ----------------
__global__ void conv_t(const float* __restrict__ xz,
                       const float* __restrict__ cw,
                       const float* __restrict__ cb,
                       float* __restrict__ xc, float* __restrict__ xcT)
{
    __shared__ float tile[32][33];
    const int b = blockIdx.z;
    const int t0 = blockIdx.y * 32;
    const int d0 = blockIdx.x * 32;
    const int tx = threadIdx.x, ty = threadIdx.y;
    const int d = d0 + tx;
    const float w0 = cw[d * 2 + 0], w1 = cw[d * 2 + 1], bsv = cb[d];
#pragma unroll
    for (int r = ty; r < 32; r += 8) {
        const int t = t0 + r;
        const long row = (long)(b * L_ + t) * (2 * D_INNER);
        float cur = xz[row + d];
        float prev = (t > 0) ? xz[row - 2 * D_INNER + d] : 0.f;
        float v = prev * w0 + cur * w1 + bsv;
        float sv = v / (1.f + __expf(-v));
        xc[(long)(b * L_ + t) * D_INNER + d] = sv;
        tile[r][tx] = sv;
    }
    __syncthreads();
#pragma unroll
    for (int r = ty; r < 32; r += 8)
        xcT[(long)(b * D_INNER + d0 + r) * L_ + t0 + tx] = tile[tx][r];
}

// ---------------- selective scan v4: SMEM-staged B/C, chunked ----------
// 128 threads = 4 warps per block; all 4 warps share the same batch b.
__global__ __launch_bounds__(128)
void scan4(const float* __restrict__ dtT, const float* __restrict__ xcT,
           const float* __restrict__ dbc,
           const float* __restrict__ A_log, const float* __restrict__ Dp,
           float* __restrict__ yT)
{
    __shared__ float bc[2][8][128];   // [buf][t in chunk][B(64) then C(64)]

    const int tid = threadIdx.x;
    const int w = tid >> 5, lane = tid & 31;
    const int gw = blockIdx.x * 4 + w;
    const int b = gw >> 10;
    const int d = gw & (D_INNER - 1);

    const float A0 = -__expf(A_log[d * D_STATE + 2 * lane]);
    const float A1 = -__expf(A_log[d * D_STATE + 2 * lane + 1]);
    const float Dd = Dp[d];

    const float* dtp = dtT + (long)d * ML + b * L_;
    const float* xp  = xcT + ((long)b * D_INNER + d) * L_;
    const float* bcsrc = dbc + (long)b * L_ * 160 + DT_RANK;  // row t: 128 floats (B then C)
    float* yp = yT + ((long)b * D_INNER + d) * L_;

    // stage chunk 0
    {
        const int j0 = tid, j1 = tid + 128;      // float4 indices (256 total)
        const int r0 = j0 >> 5, c0 = (j0 & 31) * 4;
        const int r1 = j1 >> 5, c1 = (j1 & 31) * 4;
        *(float4*)&bc[0][r0][c0] = *(const float4*)(bcsrc + (long)r0 * 160 + c0);
        *(float4*)&bc[0][r1][c1] = *(const float4*)(bcsrc + (long)r1 * 160 + c1);
    }
    __syncthreads();

    float h0 = 0.f, h1 = 0.f;
    for (int c = 0; c < L_ / 8; c++) {
        const int s = c & 1;
        const int t0 = c * 8;

        // issue loads for next chunk early (held in regs)
        float4 stg0, stg1;
        int r0s = 0, c0s = 0, r1s = 0, c1s = 0;
        const bool more = (c + 1 < L_ / 8);
        if (more) {
            const int tn = t0 + 8;
            const int j0 = tid, j1 = tid + 128;
            r0s = j0 >> 5; c0s = (j0 & 31) * 4;
            r1s = j1 >> 5; c1s = (j1 & 31) * 4;
            stg0 = *(const float4*)(bcsrc + (long)(tn + r0s) * 160 + c0s);
            stg1 = *(const float4*)(bcsrc + (long)(tn + r1s) * 160 + c1s);
        }

        float da[8], xa[8], ya[8];
        *(float4*)&da[0] = *(const float4*)(dtp + t0);
        *(float4*)&da[4] = *(const float4*)(dtp + t0 + 4);
        *(float4*)&xa[0] = *(const float4*)(xp + t0);
        *(float4*)&xa[4] = *(const float4*)(xp + t0 + 4);

#pragma unroll
        for (int q = 0; q < 8; q++) {
            const float Bx = bc[s][q][2 * lane],      By = bc[s][q][2 * lane + 1];
            const float Cx = bc[s][q][64 + 2 * lane], Cy = bc[s][q][64 + 2 * lane + 1];
            const float dtv = da[q], xv = xa[q];
            const float u = dtv * xv;
            h0 = fmaf(h0, __expf(dtv * A0), u * Bx);
            h1 = fmaf(h1, __expf(dtv * A1), u * By);
            float p = h0 * Cx + h1 * Cy;
#pragma unroll
            for (int o = 16; o; o >>= 1) p += __shfl_xor_sync(0xffffffffu, p, o);
            ya[q] = p + xv * Dd;
        }
        if (lane == 0) {
            *(float4*)(yp + t0)     = *(const float4*)&ya[0];
            *(float4*)(yp + t0 + 4) = *(const float4*)&ya[4];
        }

        if (more) {
            *(float4*)&bc[s ^ 1][r0s][c0s] = stg0;
            *(float4*)&bc[s ^ 1][r1s][c1s] = stg1;
        }
        __syncthreads();
    }
}

// ---------------- gated transpose ----------------
__global__ void gate_t(const float* __restrict__ yT, const float* __restrict__ xz,
                       float* __restrict__ y)
{
    __shared__ float tile[32][33];
    const int b = blockIdx.z;
    const int t0 = blockIdx.y * 32;
    const int d0 = blockIdx.x * 32;
    const int tx = threadIdx.x, ty = threadIdx.y;
#pragma unroll
    for (int r = ty; r < 32; r += 8)
        tile[r][tx] = yT[(long)(b * D_INNER + d0 + r) * L_ + t0 + tx];
    __syncthreads();
#pragma unroll
    for (int r = ty; r < 32; r += 8) {
        const int t = t0 + r, d = d0 + tx;
        const float zv = xz[(long)(b * L_ + t) * (2 * D_INNER) + D_INNER + d];
        y[(long)(b * L_ + t) * D_INNER + d] = tile[tx][r] * (zv / (1.f + __expf(-zv)));
    }
}

// ---------------- final FC (sums two h partial buffers) ----------------
__global__ void fc_kernel(const float* __restrict__ h, const float* __restrict__ h2,
                          const float* __restrict__ fc_w,
                          const float* __restrict__ fc_b, float* __restrict__ out)
{
    const int w = threadIdx.x >> 5;
    const int lane = threadIdx.x & 31;
    if (w >= B_ * N_CLASSES) return;
    const int b = w / N_CLASSES, c = w % N_CLASSES;
    const long off = (long)(b * L_ + (L_ - 1)) * D_MODEL;
    float s = 0.f;
    for (int k = lane; k < D_MODEL; k += 32)
        s += (h[off + k] + h2[off + k]) * fc_w[c * D_MODEL + k];
#pragma unroll
    for (int o = 16; o; o >>= 1) s += __shfl_xor_sync(0xffffffffu, s, o);
    if (lane == 0) out[b * N_CLASSES + c] = s + fc_b[c];
}

// ---------------- launch ----------------
extern "C" void kernel_launch(void* const* d_in, const int* in_sizes, int n_in,
                              void* d_out, int out_size)
{
    const float* x        = (const float*)d_in[0];
    const float* exp_w    = (const float*)d_in[1];
    const float* exp_b    = (const float*)d_in[2];
    const float* in_w     = (const float*)d_in[3];
    const float* conv_w   = (const float*)d_in[4];
    const float* conv_b   = (const float*)d_in[5];
    const float* xproj_w  = (const float*)d_in[6];
    const float* dtproj_w = (const float*)d_in[7];
    const float* dtproj_b = (const float*)d_in[8];
    const float* A_log    = (const float*)d_in[9];
    const float* Dp       = (const float*)d_in[10];
    const float* out_w    = (const float*)d_in[11];
    const float* fc_w     = (const float*)d_in[12];
    const float* fc_b     = (const float*)d_in[13];
    float* out = (float*)d_out;

    float *ph, *ph2, *pxz, *pxc, *pdbc, *py, *pdtT, *pxcT, *pyT;
    cudaGetSymbolAddress((void**)&ph,   g_h);
    cudaGetSymbolAddress((void**)&ph2,  g_h2);
    cudaGetSymbolAddress((void**)&pxz,  g_xz);
    cudaGetSymbolAddress((void**)&pxc,  g_xc);
    cudaGetSymbolAddress((void**)&pdbc, g_dbc);
    cudaGetSymbolAddress((void**)&py,   g_y);
    cudaGetSymbolAddress((void**)&pdtT, g_dtT);
    cudaGetSymbolAddress((void**)&pxcT, g_xcT);
    cudaGetSymbolAddress((void**)&pyT,  g_yT);

    const dim3 tgrid(32, 32, 4), tblk(32, 8);

    // embed: h = x @ exp_w^T + exp_b   (4096 x 512, K=128) -> ph (single buffer)
    gemm3b<0><<<dim3(D_MODEL / 128, ML / 128), 256>>>(
        x, nullptr, exp_w, exp_b, ph, nullptr, ML, D_MODEL, D_IN, D_IN, D_IN, 0);

    for (int l = 0; l < N_LAYERS; l++) {
        const float* in_w_l   = in_w     + (long)l * 2 * D_INNER * D_MODEL;
        const float* conv_w_l = conv_w   + (long)l * D_INNER * D_CONV;
        const float* conv_b_l = conv_b   + (long)l * D_INNER;
        const float* xproj_l  = xproj_w  + (long)l * 160 * D_INNER;
        const float* dtw_l    = dtproj_w + (long)l * D_INNER * DT_RANK;
        const float* dtb_l    = dtproj_b + (long)l * D_INNER;
        const float* Alog_l   = A_log    + (long)l * D_INNER * D_STATE;
        const float* Dp_l     = Dp       + (long)l * D_INNER;
        const float* out_w_l  = out_w    + (long)l * D_MODEL * D_INNER;

        // xz = (h [+h2]) @ in_w^T   (4096 x 2048, K=512)
        gemm3b<1><<<dim3(2 * D_INNER / 128, ML / 128), 256>>>(
            ph, (l > 0) ? ph2 : nullptr, in_w_l, nullptr, pxz, nullptr,
            ML, 2 * D_INNER, D_MODEL, D_MODEL, D_MODEL, 0);
        // conv + silu + transpose -> xc, xcT
        conv_t<<<tgrid, tblk>>>(pxz, conv_w_l, conv_b_l, pxc, pxcT);
        // dbc = xc @ xproj^T  (4096 x 160, K=1024) — split-K x4, atomic accumulate
        cudaMemsetAsync(pdbc, 0, (size_t)ML * 160 * sizeof(float));
        gemm3b<2><<<dim3(2, ML / 128, 4), 256>>>(
            pxc, nullptr, xproj_l, nullptr, pdbc, nullptr,
            ML, 160, 256, D_INNER, D_INNER, 3);
        // dtT = softplus(dtproj_w @ dbc[:, :32]^T + b[d])  -> [d][b*t]
        gemm3b<3><<<dim3(ML / 128, D_INNER / 128), 256>>>(
            dtw_l, nullptr, pdbc, dtb_l, pdtT, nullptr,
            D_INNER, ML, DT_RANK, DT_RANK, 160, 2);
        // selective scan (SMEM-staged B/C) -> yT (ungated)
        scan4<<<(B_ * D_INNER) / 4, 128>>>(pdtT, pxcT, pdbc, Alog_l, Dp_l, pyT);
        // gate + transpose back -> y [t][d]
        gate_t<<<tgrid, tblk>>>(pyT, pxz, py);
        // h = y @ out_w^T  (4096 x 512, K=1024) — split-K x2, per-slice buffers
        gemm3b<4><<<dim3(D_MODEL / 128, ML / 128, 2), 256>>>(
            py, nullptr, out_w_l, nullptr, ph, ph2,
            ML, D_MODEL, 512, D_INNER, D_INNER, 4);
    }

    fc_kernel<<<1, 384>>>(ph, ph2, fc_w, fc_b, out);
}

// round 16
// speedup vs baseline: 2.8194x; 1.1041x over previous
#include <cuda_runtime.h>
#include <cuda_bf16.h>
#include <stdint.h>
#include <math.h>

// ---------------- model dims ----------------
#define B_ 4
#define L_ 1024
#define D_IN 128
#define D_MODEL 512
#define N_LAYERS 2
#define N_CLASSES 3
#define D_INNER 1024
#define D_STATE 64
#define D_CONV 2
#define DT_RANK 32
#define ML (B_ * L_)

// ---------------- scratch (device globals; no allocation) ----------------
__device__ float g_h[ML * D_MODEL];
__device__ float g_h2[ML * D_MODEL];
__device__ float g_xz[ML * 2 * D_INNER];
__device__ float g_xc[ML * D_INNER];
__device__ float g_dbc[ML * 160];
__device__ float g_y[ML * D_INNER];
__device__ float g_dtT[ML * D_INNER];   // [d][b*t]
__device__ float g_xcT[ML * D_INNER];   // [b][d][t]
__device__ float g_yT[ML * D_INNER];    // [b][d][t]

__device__ __forceinline__ float softplus_f(float v) {
    return (v > 20.f) ? v : log1pf(__expf(v));
}
__device__ __forceinline__ void split2(float e0, float e1, unsigned int& hi, unsigned int& lo) {
    __nv_bfloat162 h = __floats2bfloat162_rn(e0, e1);
    float r0 = e0 - __bfloat162float(h.x);
    float r1 = e1 - __bfloat162float(h.y);
    __nv_bfloat162 l = __floats2bfloat162_rn(r0, r1);
    hi = *reinterpret_cast<unsigned int*>(&h);
    lo = *reinterpret_cast<unsigned int*>(&l);
}
__device__ __forceinline__ void mma_bf16(float* c, const unsigned int* a, const unsigned int* b) {
    asm volatile(
        "mma.sync.aligned.m16n8k16.row.col.f32.bf16.bf16.f32 "
        "{%0,%1,%2,%3}, {%4,%5,%6,%7}, {%8,%9}, {%0,%1,%2,%3};\n"
        : "+f"(c[0]), "+f"(c[1]), "+f"(c[2]), "+f"(c[3])
        : "r"(a[0]), "r"(a[1]), "r"(a[2]), "r"(a[3]),
          "r"(b[0]), "r"(b[1]));
}

// ---------------- split-bf16 (3-term) GEMM (proven R14) ----------------
// C = (A [+A2])(M,K;lda) @ W(N,K;wlda)^T for K-chunk blockIdx.z.
// act: 0 plain (+bias[n] if bias), 2 = bias[m]+softplus, 3 = atomicAdd,
//      4 = slice store: blockIdx.z==0 -> C, ==1 -> C2.
#define SKW 20

template<int TAG>
__global__ __launch_bounds__(256, 2)
void gemm3b(const float* __restrict__ A, const float* __restrict__ A2,
            const float* __restrict__ W,
            const float* __restrict__ bias, float* __restrict__ C,
            float* __restrict__ C2,
            int M, int N, int K, int lda, int wlda, int act)
{
    __shared__ unsigned int SH[2][4][128][SKW];

    const int tid = threadIdx.x;
    const int lane = tid & 31, w = tid >> 5;
    const int g = lane >> 2, l4 = lane & 3;
    const int wm = (w >> 2) * 64, wn = (w & 3) * 32;
    const int m0 = blockIdx.y * 128, n0 = blockIdx.x * 128;
    const int koff = blockIdx.z * K;

    const int lrow = tid >> 1;
    const int lcolf = (tid & 1) * 16;
    const int p0 = lcolf >> 1;
    const float* Ag = A + (long)(m0 + lrow) * lda + lcolf + koff;
    const float* Ag2 = A2 ? A2 + (long)(m0 + lrow) * lda + lcolf + koff : nullptr;
    const int wrow = n0 + lrow;
    const float* Wg = W + (long)(wrow < N ? wrow : 0) * wlda + lcolf + koff;

    float4 ra[4], rw[4];

    float acc[4][4][4];
#pragma unroll
    for (int i = 0; i < 4; i++)
#pragma unroll
        for (int j = 0; j < 4; j++)
#pragma unroll
            for (int e = 0; e < 4; e++) acc[i][j][e] = 0.f;

    const int niter = K / 32;

#pragma unroll
    for (int q = 0; q < 4; q++) {
        ra[q] = *(const float4*)(Ag + q * 4);
        if (Ag2) {
            float4 t = *(const float4*)(Ag2 + q * 4);
            ra[q].x += t.x; ra[q].y += t.y; ra[q].z += t.z; ra[q].w += t.w;
        }
        rw[q] = *(const float4*)(Wg + q * 4);
    }
#pragma unroll
    for (int q = 0; q < 4; q++) {
        unsigned int h0, l0, h1, l1;
        split2(ra[q].x, ra[q].y, h0, l0);
        split2(ra[q].z, ra[q].w, h1, l1);
        SH[0][0][lrow][p0 + 2*q]     = h0;
        SH[0][0][lrow][p0 + 2*q + 1] = h1;
        SH[0][1][lrow][p0 + 2*q]     = l0;
        SH[0][1][lrow][p0 + 2*q + 1] = l1;
        split2(rw[q].x, rw[q].y, h0, l0);
        split2(rw[q].z, rw[q].w, h1, l1);
        SH[0][2][lrow][p0 + 2*q]     = h0;
        SH[0][2][lrow][p0 + 2*q + 1] = h1;
        SH[0][3][lrow][p0 + 2*q]     = l0;
        SH[0][3][lrow][p0 + 2*q + 1] = l1;
    }
    __syncthreads();

    for (int it = 0; it < niter; it++) {
        const int s = it & 1;
        if (it + 1 < niter) {
            const int k0 = (it + 1) * 32;
#pragma unroll
            for (int q = 0; q < 4; q++) {
                ra[q] = *(const float4*)(Ag + k0 + q * 4);
                if (Ag2) {
                    float4 t = *(const float4*)(Ag2 + k0 + q * 4);
                    ra[q].x += t.x; ra[q].y += t.y; ra[q].z += t.z; ra[q].w += t.w;
                }
                rw[q] = *(const float4*)(Wg + k0 + q * 4);
            }
        }

#pragma unroll
        for (int ks = 0; ks < 2; ks++) {
            const int kb = ks * 8 + l4;
            unsigned int bh[4][2], bl[4][2];
#pragma unroll
            for (int j = 0; j < 4; j++) {
                const int r = wn + 8 * j + g;
                bh[j][0] = SH[s][2][r][kb];
                bh[j][1] = SH[s][2][r][kb + 4];
                bl[j][0] = SH[s][3][r][kb];
                bl[j][1] = SH[s][3][r][kb + 4];
            }
#pragma unroll
            for (int i = 0; i < 4; i++) {
                const int r0 = wm + 16 * i + g, r1 = r0 + 8;
                unsigned int ah[4], al[4];
                ah[0] = SH[s][0][r0][kb];     ah[1] = SH[s][0][r1][kb];
                ah[2] = SH[s][0][r0][kb + 4]; ah[3] = SH[s][0][r1][kb + 4];
                al[0] = SH[s][1][r0][kb];     al[1] = SH[s][1][r1][kb];
                al[2] = SH[s][1][r0][kb + 4]; al[3] = SH[s][1][r1][kb + 4];
#pragma unroll
                for (int j = 0; j < 4; j++) mma_bf16(acc[i][j], ah, bh[j]);
#pragma unroll
                for (int j = 0; j < 4; j++) mma_bf16(acc[i][j], ah, bl[j]);
#pragma unroll
                for (int j = 0; j < 4; j++) mma_bf16(acc[i][j], al, bh[j]);
            }
        }

        if (it + 1 < niter) {
            const int s2 = (it + 1) & 1;
#pragma unroll
            for (int q = 0; q < 4; q++) {
                unsigned int h0, l0, h1, l1;
                split2(ra[q].x, ra[q].y, h0, l0);
                split2(ra[q].z, ra[q].w, h1, l1);
                SH[s2][0][lrow][p0 + 2*q]     = h0;
                SH[s2][0][lrow][p0 + 2*q + 1] = h1;
                SH[s2][1][lrow][p0 + 2*q]     = l0;
                SH[s2][1][lrow][p0 + 2*q + 1] = l1;
                split2(rw[q].x, rw[q].y, h0, l0);
                split2(rw[q].z, rw[q].w, h1, l1);
                SH[s2][2][lrow][p0 + 2*q]     = h0;
                SH[s2][2][lrow][p0 + 2*q + 1] = h1;
                SH[s2][3][lrow][p0 + 2*q]     = l0;
                SH[s2][3][lrow][p0 + 2*q + 1] = l1;
            }
        }
        __syncthreads();
    }

    float* Cout = (act == 4 && blockIdx.z == 1) ? C2 : C;
#pragma unroll
    for (int i = 0; i < 4; i++) {
        const int mr0 = m0 + wm + 16 * i + g;
        const int mr1 = mr0 + 8;
        float rb0 = 0.f, rb1 = 0.f;
        if (act == 2) { rb0 = bias[mr0]; rb1 = bias[mr1]; }
#pragma unroll
        for (int j = 0; j < 4; j++) {
            const int n = n0 + wn + 8 * j + 2 * l4;
            if (n < N) {
                float v0 = acc[i][j][0], v1 = acc[i][j][1];
                float v2 = acc[i][j][2], v3 = acc[i][j][3];
                if (act == 3) {
                    atomicAdd(C + (long)mr0 * N + n,     v0);
                    atomicAdd(C + (long)mr0 * N + n + 1, v1);
                    atomicAdd(C + (long)mr1 * N + n,     v2);
                    atomicAdd(C + (long)mr1 * N + n + 1, v3);
                } else {
                    if (act == 2) {
                        v0 = softplus_f(v0 + rb0); v1 = softplus_f(v1 + rb0);
                        v2 = softplus_f(v2 + rb1); v3 = softplus_f(v3 + rb1);
                    } else if (act == 0 && bias) {
                        float b0 = bias[n], b1 = bias[n + 1];
                        v0 += b0; v1 += b1; v2 += b0; v3 += b1;
                    }
                    *(float2*)(Cout + (long)mr0 * N + n) = make_float2(v0, v1);
                    *(float2*)(Cout + (long)mr1 * N + n) = make_float2(v2, v3);
                }
            }
        }
    }
}

// ---------------- conv + silu + transpose ----------------
__global__ void conv_t(const float* __restrict__ xz,
                       const float* __restrict__ cw,
                       const float* __restrict__ cb,
                       float* __restrict__ xc, float* __restrict__ xcT)
{
    __shared__ float tile[32][33];
    const int b = blockIdx.z;
    const int t0 = blockIdx.y * 32;
    const int d0 = blockIdx.x * 32;
    const int tx = threadIdx.x, ty = threadIdx.y;
    const int d = d0 + tx;
    const float w0 = cw[d * 2 + 0], w1 = cw[d * 2 + 1], bsv = cb[d];
#pragma unroll
    for (int r = ty; r < 32; r += 8) {
        const int t = t0 + r;
        const long row = (long)(b * L_ + t) * (2 * D_INNER);
        float cur = xz[row + d];
        float prev = (t > 0) ? xz[row - 2 * D_INNER + d] : 0.f;
        float v = prev * w0 + cur * w1 + bsv;
        float sv = v / (1.f + __expf(-v));
        xc[(long)(b * L_ + t) * D_INNER + d] = sv;
        tile[r][tx] = sv;
    }
    __syncthreads();
#pragma unroll
    for (int r = ty; r < 32; r += 8)
        xcT[(long)(b * D_INNER + d0 + r) * L_ + t0 + tx] = tile[tx][r];
}

// ---------------- selective scan v5: 2 channels/warp, 4 states/lane ----------
// Block = 128 threads = 4 warps = 8 channels, all same batch b.
// Lane: half = lane/16 selects channel; li = lane%16 owns states 4li..4li+3.
__global__ __launch_bounds__(128)
void scan5(const float* __restrict__ dtT, const float* __restrict__ xcT,
           const float* __restrict__ dbc,
           const float* __restrict__ A_log, const float* __restrict__ Dp,
           float* __restrict__ yT)
{
    __shared__ float bc[2][8][128];   // [buf][t in chunk][B(64) then C(64)]

    const int tid = threadIdx.x;
    const int w = tid >> 5, lane = tid & 31;
    const int half = lane >> 4, li = lane & 15;
    const int b = blockIdx.x >> 7;                       // 4 batches x 128 groups
    const int d = (blockIdx.x & 127) * 8 + w * 2 + half; // 8 channels per block

    float Ar[4];
#pragma unroll
    for (int j = 0; j < 4; j++)
        Ar[j] = -__expf(A_log[d * D_STATE + 4 * li + j]);
    const float Dd = Dp[d];

    const float* dtp = dtT + (long)d * ML + b * L_;
    const float* xp  = xcT + ((long)b * D_INNER + d) * L_;
    const float* bcsrc = dbc + (long)b * L_ * 160 + DT_RANK;
    float* yp = yT + ((long)b * D_INNER + d) * L_;

    // stage chunk 0 (1024 floats = 256 float4 over 128 threads)
    {
        const int j0 = tid, j1 = tid + 128;
        const int r0 = j0 >> 5, c0 = (j0 & 31) * 4;
        const int r1 = j1 >> 5, c1 = (j1 & 31) * 4;
        *(float4*)&bc[0][r0][c0] = *(const float4*)(bcsrc + (long)r0 * 160 + c0);
        *(float4*)&bc[0][r1][c1] = *(const float4*)(bcsrc + (long)r1 * 160 + c1);
    }
    __syncthreads();

    float h0 = 0.f, h1 = 0.f, h2 = 0.f, h3 = 0.f;
    for (int c = 0; c < L_ / 8; c++) {
        const int s = c & 1;
        const int t0 = c * 8;

        float4 stg0, stg1;
        int r0s = 0, c0s = 0, r1s = 0, c1s = 0;
        const bool more = (c + 1 < L_ / 8);
        if (more) {
            const int tn = t0 + 8;
            const int j0 = tid, j1 = tid + 128;
            r0s = j0 >> 5; c0s = (j0 & 31) * 4;
            r1s = j1 >> 5; c1s = (j1 & 31) * 4;
            stg0 = *(const float4*)(bcsrc + (long)(tn + r0s) * 160 + c0s);
            stg1 = *(const float4*)(bcsrc + (long)(tn + r1s) * 160 + c1s);
        }

        float da[8], xa[8], ya[8];
        *(float4*)&da[0] = *(const float4*)(dtp + t0);
        *(float4*)&da[4] = *(const float4*)(dtp + t0 + 4);
        *(float4*)&xa[0] = *(const float4*)(xp + t0);
        *(float4*)&xa[4] = *(const float4*)(xp + t0 + 4);

#pragma unroll
        for (int q = 0; q < 8; q++) {
            const float4 Bv = *(const float4*)&bc[s][q][4 * li];
            const float4 Cv = *(const float4*)&bc[s][q][64 + 4 * li];
            const float dtv = da[q], xv = xa[q];
            const float u = dtv * xv;
            h0 = fmaf(h0, __expf(dtv * Ar[0]), u * Bv.x);
            h1 = fmaf(h1, __expf(dtv * Ar[1]), u * Bv.y);
            h2 = fmaf(h2, __expf(dtv * Ar[2]), u * Bv.z);
            h3 = fmaf(h3, __expf(dtv * Ar[3]), u * Bv.w);
            float p = h0 * Cv.x + h1 * Cv.y + h2 * Cv.z + h3 * Cv.w;
#pragma unroll
            for (int o = 8; o; o >>= 1) p += __shfl_xor_sync(0xffffffffu, p, o);
            ya[q] = p + xv * Dd;
        }
        if (li == 0) {
            *(float4*)(yp + t0)     = *(const float4*)&ya[0];
            *(float4*)(yp + t0 + 4) = *(const float4*)&ya[4];
        }

        if (more) {
            *(float4*)&bc[s ^ 1][r0s][c0s] = stg0;
            *(float4*)&bc[s ^ 1][r1s][c1s] = stg1;
        }
        __syncthreads();
    }
}

// ---------------- gated transpose ----------------
__global__ void gate_t(const float* __restrict__ yT, const float* __restrict__ xz,
                       float* __restrict__ y)
{
    __shared__ float tile[32][33];
    const int b = blockIdx.z;
    const int t0 = blockIdx.y * 32;
    const int d0 = blockIdx.x * 32;
    const int tx = threadIdx.x, ty = threadIdx.y;
#pragma unroll
    for (int r = ty; r < 32; r += 8)
        tile[r][tx] = yT[(long)(b * D_INNER + d0 + r) * L_ + t0 + tx];
    __syncthreads();
#pragma unroll
    for (int r = ty; r < 32; r += 8) {
        const int t = t0 + r, d = d0 + tx;
        const float zv = xz[(long)(b * L_ + t) * (2 * D_INNER) + D_INNER + d];
        y[(long)(b * L_ + t) * D_INNER + d] = tile[tx][r] * (zv / (1.f + __expf(-zv)));
    }
}

// ---------------- final FC ----------------
__global__ void fc_kernel(const float* __restrict__ h, const float* __restrict__ h2,
                          const float* __restrict__ fc_w,
                          const float* __restrict__ fc_b, float* __restrict__ out)
{
    const int w = threadIdx.x >> 5;
    const int lane = threadIdx.x & 31;
    if (w >= B_ * N_CLASSES) return;
    const int b = w / N_CLASSES, c = w % N_CLASSES;
    const long off = (long)(b * L_ + (L_ - 1)) * D_MODEL;
    float s = 0.f;
    for (int k = lane; k < D_MODEL; k += 32)
        s += (h[off + k] + h2[off + k]) * fc_w[c * D_MODEL + k];
#pragma unroll
    for (int o = 16; o; o >>= 1) s += __shfl_xor_sync(0xffffffffu, s, o);
    if (lane == 0) out[b * N_CLASSES + c] = s + fc_b[c];
}

// ---------------- launch ----------------
extern "C" void kernel_launch(void* const* d_in, const int* in_sizes, int n_in,
                              void* d_out, int out_size)
{
    const float* x        = (const float*)d_in[0];
    const float* exp_w    = (const float*)d_in[1];
    const float* exp_b    = (const float*)d_in[2];
    const float* in_w     = (const float*)d_in[3];
    const float* conv_w   = (const float*)d_in[4];
    const float* conv_b   = (const float*)d_in[5];
    const float* xproj_w  = (const float*)d_in[6];
    const float* dtproj_w = (const float*)d_in[7];
    const float* dtproj_b = (const float*)d_in[8];
    const float* A_log    = (const float*)d_in[9];
    const float* Dp       = (const float*)d_in[10];
    const float* out_w    = (const float*)d_in[11];
    const float* fc_w     = (const float*)d_in[12];
    const float* fc_b     = (const float*)d_in[13];
    float* out = (float*)d_out;

    float *ph, *ph2, *pxz, *pxc, *pdbc, *py, *pdtT, *pxcT, *pyT;
    cudaGetSymbolAddress((void**)&ph,   g_h);
    cudaGetSymbolAddress((void**)&ph2,  g_h2);
    cudaGetSymbolAddress((void**)&pxz,  g_xz);
    cudaGetSymbolAddress((void**)&pxc,  g_xc);
    cudaGetSymbolAddress((void**)&pdbc, g_dbc);
    cudaGetSymbolAddress((void**)&py,   g_y);
    cudaGetSymbolAddress((void**)&pdtT, g_dtT);
    cudaGetSymbolAddress((void**)&pxcT, g_xcT);
    cudaGetSymbolAddress((void**)&pyT,  g_yT);

    const dim3 tgrid(32, 32, 4), tblk(32, 8);

    // embed: h = x @ exp_w^T + exp_b   (4096 x 512, K=128)
    gemm3b<0><<<dim3(D_MODEL / 128, ML / 128), 256>>>(
        x, nullptr, exp_w, exp_b, ph, nullptr, ML, D_MODEL, D_IN, D_IN, D_IN, 0);

    for (int l = 0; l < N_LAYERS; l++) {
        const float* in_w_l   = in_w     + (long)l * 2 * D_INNER * D_MODEL;
        const float* conv_w_l = conv_w   + (long)l * D_INNER * D_CONV;
        const float* conv_b_l = conv_b   + (long)l * D_INNER;
        const float* xproj_l  = xproj_w  + (long)l * 160 * D_INNER;
        const float* dtw_l    = dtproj_w + (long)l * D_INNER * DT_RANK;
        const float* dtb_l    = dtproj_b + (long)l * D_INNER;
        const float* Alog_l   = A_log    + (long)l * D_INNER * D_STATE;
        const float* Dp_l     = Dp       + (long)l * D_INNER;
        const float* out_w_l  = out_w    + (long)l * D_MODEL * D_INNER;

        // xz = (h [+h2]) @ in_w^T   (4096 x 2048, K=512)
        gemm3b<1><<<dim3(2 * D_INNER / 128, ML / 128), 256>>>(
            ph, (l > 0) ? ph2 : nullptr, in_w_l, nullptr, pxz, nullptr,
            ML, 2 * D_INNER, D_MODEL, D_MODEL, D_MODEL, 0);
        // conv + silu + transpose -> xc, xcT
        conv_t<<<tgrid, tblk>>>(pxz, conv_w_l, conv_b_l, pxc, pxcT);
        // dbc = xc @ xproj^T  (4096 x 160, K=1024) — split-K x4, atomic accumulate
        cudaMemsetAsync(pdbc, 0, (size_t)ML * 160 * sizeof(float));
        gemm3b<2><<<dim3(2, ML / 128, 4), 256>>>(
            pxc, nullptr, xproj_l, nullptr, pdbc, nullptr,
            ML, 160, 256, D_INNER, D_INNER, 3);
        // dtT = softplus(dtproj_w @ dbc[:, :32]^T + b[d])  -> [d][b*t]
        gemm3b<3><<<dim3(ML / 128, D_INNER / 128), 256>>>(
            dtw_l, nullptr, pdbc, dtb_l, pdtT, nullptr,
            D_INNER, ML, DT_RANK, DT_RANK, 160, 2);
        // selective scan (2 ch/warp, SMEM B/C) -> yT (ungated)
        scan5<<<(B_ * D_INNER) / 8, 128>>>(pdtT, pxcT, pdbc, Alog_l, Dp_l, pyT);
        // gate + transpose back -> y [t][d]
        gate_t<<<tgrid, tblk>>>(pyT, pxz, py);
        // h = y @ out_w^T  (4096 x 512, K=1024) — split-K x2, per-slice buffers
        gemm3b<4><<<dim3(D_MODEL / 128, ML / 128, 2), 256>>>(
            py, nullptr, out_w_l, nullptr, ph, ph2,
            ML, D_MODEL, 512, D_INNER, D_INNER, 4);
    }

    fc_kernel<<<1, 384>>>(ph, ph2, fc_w, fc_b, out);
}